// round 2
// baseline (speedup 1.0000x reference)
#include <cuda_runtime.h>
#include <math.h>

#define NN 50000
#define EE 800000
#define ETOT (EE + NN)
#define BB 64
#define F_IN 128
#define POS 16
#define ENH 144
#define HC 256
#define OUT_DIM 128

// ---------------- scratch (device globals; no allocation allowed) ----------------
__device__ float g_h0[(size_t)NN * ENH];
__device__ float g_hA[(size_t)NN * HC];
__device__ float g_hB[(size_t)NN * HC];
__device__ float g_as[NN * 4];
__device__ float g_ad[NN * 4];
__device__ int   g_deg[NN];
__device__ int   g_off[NN + 1];
__device__ int   g_cur[NN];
__device__ int   g_csr[ETOT];
__device__ int   g_counts[BB];
__device__ int   g_starts[BB];
__device__ int   g_gs[BB];
__device__ float g_bn1[512];
__device__ float g_bn2[512];
__device__ float g_prm1[512];
__device__ float g_prm2[512];
__device__ float g_pool[BB * HC];

// ---------------- zero scratch ----------------
__global__ void k_zero() {
    int stride = gridDim.x * blockDim.x;
    int i = blockIdx.x * blockDim.x + threadIdx.x;
    for (int j = i; j < NN; j += stride) g_deg[j] = 0;
    for (int j = i; j < BB; j += stride) g_counts[j] = 0;
    for (int j = i; j < 512; j += stride) { g_bn1[j] = 0.f; g_bn2[j] = 0.f; }
    for (int j = i; j < BB * HC; j += stride) g_pool[j] = 0.f;
}

// ---------------- graph counts ----------------
__global__ void k_counts(const int* __restrict__ batch) {
    __shared__ int sm[BB];
    int t = threadIdx.x;
    if (t < BB) sm[t] = 0;
    __syncthreads();
    int i = blockIdx.x * blockDim.x + t;
    if (i < NN) atomicAdd(&sm[batch[i]], 1);
    __syncthreads();
    if (t < BB && sm[t]) atomicAdd(&g_counts[t], sm[t]);
}

__global__ void k_graph_meta() {
    if (threadIdx.x == 0 && blockIdx.x == 0) {
        int acc = 0;
        for (int b = 0; b < BB; b++) {
            int c = g_counts[b];
            g_starts[b] = acc;
            acc += c;
            g_gs[b] = (int)ceilf(sqrtf((float)c));   // matches jnp.ceil(jnp.sqrt(f32))
        }
    }
}

// ---------------- positional encoding + concat ----------------
__global__ void k_build_h0(const float* __restrict__ x, const int* __restrict__ batch,
                           const float* __restrict__ Wpos, const float* __restrict__ bpos) {
    long idx = (long)blockIdx.x * blockDim.x + threadIdx.x;
    if (idx >= (long)NN * ENH) return;
    int n = (int)(idx / ENH);
    int j = (int)(idx % ENH);
    if (j < F_IN) {
        g_h0[(size_t)n * ENH + j] = x[(size_t)n * F_IN + j];
    } else {
        int jj = j - F_IN;
        int b = batch[n];
        int g = g_gs[b];
        int i = n - g_starts[b];
        int row = i / g;
        int col = i - row * g;
        float denom = (float)(g - 1 > 1 ? g - 1 : 1);
        float p0 = (float)row / denom;
        float p1 = (float)col / denom;
        g_h0[(size_t)n * ENH + j] = p0 * Wpos[jj] + p1 * Wpos[POS + jj] + bpos[jj];
    }
}

// ---------------- CSR build ----------------
__global__ void k_degree(const int* __restrict__ ei) {
    int e = blockIdx.x * blockDim.x + threadIdx.x;
    if (e >= ETOT) return;
    int d = (e < EE) ? ei[EE + e] : (e - EE);
    atomicAdd(&g_deg[d], 1);
}

__global__ void k_scan_deg() {
    __shared__ int sm[1024];
    __shared__ int s_carry;
    int t = threadIdx.x;
    if (t == 0) s_carry = 0;
    __syncthreads();
    for (int base = 0; base < NN; base += 1024) {
        int i = base + t;
        int v = (i < NN) ? g_deg[i] : 0;
        sm[t] = v;
        __syncthreads();
        #pragma unroll
        for (int off = 1; off < 1024; off <<= 1) {
            int xv = (t >= off) ? sm[t - off] : 0;
            __syncthreads();
            sm[t] += xv;
            __syncthreads();
        }
        int carry = s_carry;
        int excl = carry + sm[t] - v;
        if (i < NN) { g_off[i] = excl; g_cur[i] = excl; }
        __syncthreads();
        if (t == 0) s_carry = carry + sm[1023];
        __syncthreads();
    }
    if (t == 0) g_off[NN] = s_carry;
}

__global__ void k_scatter(const int* __restrict__ ei) {
    int e = blockIdx.x * blockDim.x + threadIdx.x;
    if (e >= ETOT) return;
    int s, d;
    if (e < EE) { s = ei[e]; d = ei[EE + e]; }
    else { s = d = e - EE; }
    int p = atomicAdd(&g_cur[d], 1);
    g_csr[p] = s;
}

// ---------------- GEMM: C[M,256] = A[M,K] @ B[K,256] ----------------
template <int K>
__global__ void k_gemm(const float* __restrict__ A, const float* __restrict__ B,
                       float* __restrict__ C, int M) {
    const int BM = 64, BN = 64, BK = 16;
    __shared__ float As[BK][BM + 4];
    __shared__ float Bs[BK][BN + 4];
    int tid = threadIdx.x;
    int tx = tid % 16, ty = tid / 16;
    int row0 = blockIdx.x * BM;
    int col0 = blockIdx.y * BN;
    float acc[4][4];
    #pragma unroll
    for (int i = 0; i < 4; i++)
        #pragma unroll
        for (int j = 0; j < 4; j++) acc[i][j] = 0.f;

    for (int k0 = 0; k0 < K; k0 += BK) {
        {
            int r = tid >> 2;
            int kk = (tid & 3) * 4;
            int gr = row0 + r;
            float4 v = make_float4(0.f, 0.f, 0.f, 0.f);
            if (gr < M) v = *(const float4*)&A[(size_t)gr * K + k0 + kk];
            As[kk + 0][r] = v.x; As[kk + 1][r] = v.y;
            As[kk + 2][r] = v.z; As[kk + 3][r] = v.w;
        }
        {
            int kk = tid >> 4;
            int c = (tid & 15) * 4;
            float4 v = *(const float4*)&B[(size_t)(k0 + kk) * HC + col0 + c];
            Bs[kk][c + 0] = v.x; Bs[kk][c + 1] = v.y;
            Bs[kk][c + 2] = v.z; Bs[kk][c + 3] = v.w;
        }
        __syncthreads();
        #pragma unroll
        for (int kk = 0; kk < BK; kk++) {
            float a[4], b[4];
            #pragma unroll
            for (int i = 0; i < 4; i++) a[i] = As[kk][ty * 4 + i];
            #pragma unroll
            for (int j = 0; j < 4; j++) b[j] = Bs[kk][tx * 4 + j];
            #pragma unroll
            for (int i = 0; i < 4; i++)
                #pragma unroll
                for (int j = 0; j < 4; j++) acc[i][j] += a[i] * b[j];
        }
        __syncthreads();
    }
    #pragma unroll
    for (int i = 0; i < 4; i++) {
        int gr = row0 + ty * 4 + i;
        if (gr < M) {
            float4 v = make_float4(acc[i][0], acc[i][1], acc[i][2], acc[i][3]);
            *(float4*)&C[(size_t)gr * HC + col0 + tx * 4] = v;
        }
    }
}

// ---------------- attention coefficients: as/ad [N,4] ----------------
__global__ void k_attn(const float* __restrict__ h, const float* __restrict__ a_src,
                       const float* __restrict__ a_dst) {
    int gw = (blockIdx.x * blockDim.x + threadIdx.x) >> 5;
    int lane = threadIdx.x & 31;
    if (gw >= NN) return;
    const float* row = h + (size_t)gw * HC;
    float ps[4] = {0, 0, 0, 0}, pd[4] = {0, 0, 0, 0};
    #pragma unroll
    for (int k = 0; k < 8; k++) {
        int ch = lane + 32 * k;
        int hd = k >> 1;
        float v = row[ch];
        ps[hd] += v * a_src[ch];
        pd[hd] += v * a_dst[ch];
    }
    #pragma unroll
    for (int hd = 0; hd < 4; hd++) {
        #pragma unroll
        for (int off = 16; off; off >>= 1) {
            ps[hd] += __shfl_xor_sync(0xFFFFFFFFu, ps[hd], off);
            pd[hd] += __shfl_xor_sync(0xFFFFFFFFu, pd[hd], off);
        }
    }
    if (lane < 4) {
        g_as[gw * 4 + lane] = ps[lane];
        g_ad[gw * 4 + lane] = pd[lane];
    }
}

// ---------------- softmax-aggregate: warp per dst node ----------------
__global__ void k_agg(const float* __restrict__ h, const float* __restrict__ bias,
                      float* __restrict__ out) {
    int wp = threadIdx.x >> 5;
    int lane = threadIdx.x & 31;
    int node = blockIdx.x * 8 + wp;
    if (node >= NN) return;
    __shared__ float wsm[8][32][4];

    int beg = g_off[node], end = g_off[node + 1];
    float ad0 = g_ad[node * 4 + 0], ad1 = g_ad[node * 4 + 1];
    float ad2 = g_ad[node * 4 + 2], ad3 = g_ad[node * 4 + 3];

    // pass 1: per-head max of leaky_relu(as[src]+ad[dst])
    float m0 = -1e30f, m1 = -1e30f, m2 = -1e30f, m3 = -1e30f;
    for (int j = beg + lane; j < end; j += 32) {
        int s = g_csr[j];
        const float* as = &g_as[s * 4];
        float v0 = as[0] + ad0; v0 = v0 > 0.f ? v0 : 0.2f * v0; m0 = fmaxf(m0, v0);
        float v1 = as[1] + ad1; v1 = v1 > 0.f ? v1 : 0.2f * v1; m1 = fmaxf(m1, v1);
        float v2 = as[2] + ad2; v2 = v2 > 0.f ? v2 : 0.2f * v2; m2 = fmaxf(m2, v2);
        float v3 = as[3] + ad3; v3 = v3 > 0.f ? v3 : 0.2f * v3; m3 = fmaxf(m3, v3);
    }
    #pragma unroll
    for (int off = 16; off; off >>= 1) {
        m0 = fmaxf(m0, __shfl_xor_sync(0xFFFFFFFFu, m0, off));
        m1 = fmaxf(m1, __shfl_xor_sync(0xFFFFFFFFu, m1, off));
        m2 = fmaxf(m2, __shfl_xor_sync(0xFFFFFFFFu, m2, off));
        m3 = fmaxf(m3, __shfl_xor_sync(0xFFFFFFFFu, m3, off));
    }

    // pass 2: exp weights + weighted accumulation over 256 channels
    float acc[8] = {0, 0, 0, 0, 0, 0, 0, 0};
    float sw0 = 0.f, sw1 = 0.f, sw2 = 0.f, sw3 = 0.f;
    for (int base = beg; base < end; base += 32) {
        int j = base + lane;
        float w0 = 0.f, w1 = 0.f, w2 = 0.f, w3 = 0.f;
        if (j < end) {
            int s = g_csr[j];
            const float* as = &g_as[s * 4];
            float v0 = as[0] + ad0; v0 = v0 > 0.f ? v0 : 0.2f * v0; w0 = __expf(v0 - m0);
            float v1 = as[1] + ad1; v1 = v1 > 0.f ? v1 : 0.2f * v1; w1 = __expf(v1 - m1);
            float v2 = as[2] + ad2; v2 = v2 > 0.f ? v2 : 0.2f * v2; w2 = __expf(v2 - m2);
            float v3 = as[3] + ad3; v3 = v3 > 0.f ? v3 : 0.2f * v3; w3 = __expf(v3 - m3);
        }
        wsm[wp][lane][0] = w0; wsm[wp][lane][1] = w1;
        wsm[wp][lane][2] = w2; wsm[wp][lane][3] = w3;
        sw0 += w0; sw1 += w1; sw2 += w2; sw3 += w3;
        __syncwarp();
        int cnt = end - base; if (cnt > 32) cnt = 32;
        for (int t = 0; t < cnt; t++) {
            int ss = g_csr[base + t];
            float wv0 = wsm[wp][t][0], wv1 = wsm[wp][t][1];
            float wv2 = wsm[wp][t][2], wv3 = wsm[wp][t][3];
            const float* hp = &h[(size_t)ss * HC + lane];
            acc[0] += wv0 * hp[0];   acc[1] += wv0 * hp[32];
            acc[2] += wv1 * hp[64];  acc[3] += wv1 * hp[96];
            acc[4] += wv2 * hp[128]; acc[5] += wv2 * hp[160];
            acc[6] += wv3 * hp[192]; acc[7] += wv3 * hp[224];
        }
        __syncwarp();
    }
    #pragma unroll
    for (int off = 16; off; off >>= 1) {
        sw0 += __shfl_xor_sync(0xFFFFFFFFu, sw0, off);
        sw1 += __shfl_xor_sync(0xFFFFFFFFu, sw1, off);
        sw2 += __shfl_xor_sync(0xFFFFFFFFu, sw2, off);
        sw3 += __shfl_xor_sync(0xFFFFFFFFu, sw3, off);
    }
    float i0 = 1.f / sw0, i1 = 1.f / sw1, i2 = 1.f / sw2, i3 = 1.f / sw3;
    float* op = &out[(size_t)node * HC + lane];
    op[0]   = acc[0] * i0 + bias[lane];
    op[32]  = acc[1] * i0 + bias[lane + 32];
    op[64]  = acc[2] * i1 + bias[lane + 64];
    op[96]  = acc[3] * i1 + bias[lane + 96];
    op[128] = acc[4] * i2 + bias[lane + 128];
    op[160] = acc[5] * i2 + bias[lane + 160];
    op[192] = acc[6] * i3 + bias[lane + 192];
    op[224] = acc[7] * i3 + bias[lane + 224];
}

// ---------------- batch norm ----------------
__global__ void k_bn_stats(const float* __restrict__ x, float* __restrict__ sums) {
    int ch = threadIdx.x;
    float s = 0.f, s2 = 0.f;
    for (int r = blockIdx.x; r < NN; r += gridDim.x) {
        float v = x[(size_t)r * HC + ch];
        s += v; s2 += v * v;
    }
    atomicAdd(&sums[ch], s);
    atomicAdd(&sums[HC + ch], s2);
}

__global__ void k_bn_fin(const float* __restrict__ sums, const float* __restrict__ gamma,
                         const float* __restrict__ beta, float* __restrict__ prm) {
    int ch = threadIdx.x;
    float mean = sums[ch] / (float)NN;
    float var = sums[HC + ch] / (float)NN - mean * mean;
    float inv = rsqrtf(var + 1e-5f);
    float sc = gamma[ch] * inv;
    prm[ch] = sc;
    prm[HC + ch] = beta[ch] - mean * sc;
}

__global__ void k_bn_elu(float* __restrict__ x, const float* __restrict__ prm) {
    long idx = (long)blockIdx.x * blockDim.x + threadIdx.x;
    if (idx >= (long)NN * HC) return;
    int ch = (int)(idx & (HC - 1));
    float v = x[idx] * prm[ch] + prm[HC + ch];
    x[idx] = v > 0.f ? v : (__expf(v) - 1.f);
}

// ---------------- pooling + FC ----------------
__global__ void k_pool(const float* __restrict__ x) {
    int g = blockIdx.x, part = blockIdx.y, ch = threadIdx.x;
    int beg = g_starts[g], cnt = g_counts[g];
    float s = 0.f;
    for (int r = part; r < cnt; r += 8)
        s += x[(size_t)(beg + r) * HC + ch];
    atomicAdd(&g_pool[g * HC + ch], s);
}

__global__ void k_fc(const float* __restrict__ Wfc, const float* __restrict__ bfc,
                     float* __restrict__ out) {
    int g = blockIdx.x, o = threadIdx.x;
    __shared__ float ps[HC];
    float invc = 1.f / (float)g_counts[g];
    for (int c = o; c < HC; c += OUT_DIM) ps[c] = g_pool[g * HC + c] * invc;
    __syncthreads();
    float acc = bfc[o];
    #pragma unroll 8
    for (int c = 0; c < HC; c++) acc += ps[c] * Wfc[c * OUT_DIM + o];
    out[g * OUT_DIM + o] = acc;
}

// ---------------- launch ----------------
extern "C" void kernel_launch(void* const* d_in, const int* in_sizes, int n_in,
                              void* d_out, int out_size) {
    const float* x       = (const float*)d_in[0];
    const int*   ei      = (const int*)d_in[1];
    const int*   batch   = (const int*)d_in[2];
    const float* W_pos   = (const float*)d_in[3];
    const float* b_pos   = (const float*)d_in[4];
    const float* W1      = (const float*)d_in[5];
    const float* a_src1  = (const float*)d_in[6];
    const float* a_dst1  = (const float*)d_in[7];
    const float* b1      = (const float*)d_in[8];
    const float* gamma1  = (const float*)d_in[9];
    const float* beta1   = (const float*)d_in[10];
    const float* W2      = (const float*)d_in[11];
    const float* a_src2  = (const float*)d_in[12];
    const float* a_dst2  = (const float*)d_in[13];
    const float* b2      = (const float*)d_in[14];
    const float* gamma2  = (const float*)d_in[15];
    const float* beta2   = (const float*)d_in[16];
    const float* W_fc    = (const float*)d_in[17];
    const float* b_fc    = (const float*)d_in[18];
    float* out = (float*)d_out;

    float *h0, *hA, *hB, *bn1, *bn2, *prm1, *prm2;
    cudaGetSymbolAddress((void**)&h0, g_h0);
    cudaGetSymbolAddress((void**)&hA, g_hA);
    cudaGetSymbolAddress((void**)&hB, g_hB);
    cudaGetSymbolAddress((void**)&bn1, g_bn1);
    cudaGetSymbolAddress((void**)&bn2, g_bn2);
    cudaGetSymbolAddress((void**)&prm1, g_prm1);
    cudaGetSymbolAddress((void**)&prm2, g_prm2);

    // setup
    k_zero<<<256, 256>>>();
    k_counts<<<(NN + 255) / 256, 256>>>(batch);
    k_graph_meta<<<1, 32>>>();
    k_build_h0<<<(int)(((long)NN * ENH + 255) / 256), 256>>>(x, batch, W_pos, b_pos);
    k_degree<<<(ETOT + 255) / 256, 256>>>(ei);
    k_scan_deg<<<1, 1024>>>();
    k_scatter<<<(ETOT + 255) / 256, 256>>>(ei);

    // layer 1
    dim3 gg1((NN + 63) / 64, 4);
    k_gemm<ENH><<<gg1, 256>>>(h0, W1, hA, NN);
    k_attn<<<(NN * 32 + 255) / 256, 256>>>(hA, a_src1, a_dst1);
    k_agg<<<(NN + 7) / 8, 256>>>(hA, b1, hB);
    k_bn_stats<<<512, 256>>>(hB, bn1);
    k_bn_fin<<<1, 256>>>(bn1, gamma1, beta1, prm1);
    k_bn_elu<<<(int)(((long)NN * HC + 255) / 256), 256>>>(hB, prm1);

    // layer 2
    dim3 gg2((NN + 63) / 64, 4);
    k_gemm<HC><<<gg2, 256>>>(hB, W2, hA, NN);
    k_attn<<<(NN * 32 + 255) / 256, 256>>>(hA, a_src2, a_dst2);
    k_agg<<<(NN + 7) / 8, 256>>>(hA, b2, hB);
    k_bn_stats<<<512, 256>>>(hB, bn2);
    k_bn_fin<<<1, 256>>>(bn2, gamma2, beta2, prm2);
    k_bn_elu<<<(int)(((long)NN * HC + 255) / 256), 256>>>(hB, prm2);

    // pool + fc
    dim3 gp(BB, 8);
    k_pool<<<gp, 256>>>(hB);
    k_fc<<<BB, OUT_DIM>>>(W_fc, b_fc, out);
}

// round 3
// speedup vs baseline: 1.2857x; 1.2857x over previous
#include <cuda_runtime.h>
#include <math.h>
#include <mma.h>

using namespace nvcuda;

#define NN 50000
#define EE 800000
#define ETOT (EE + NN)
#define BB 64
#define F_IN 128
#define POS 16
#define ENH 144
#define HC 256
#define OUT_DIM 128

// ---------------- scratch (device globals; no allocation allowed) ----------------
__device__ float g_hA[(size_t)NN * HC];
__device__ float g_hB[(size_t)NN * HC];
__device__ float g_as[NN * 4];
__device__ float g_ad[NN * 4];
__device__ int   g_deg[NN];
__device__ int   g_off[NN + 1];
__device__ int   g_cur[NN];
__device__ int   g_csr[ETOT];
__device__ int   g_counts[BB];
__device__ int   g_starts[BB];
__device__ int   g_gs[BB];
__device__ float g_bn1[512];
__device__ float g_bn2[512];
__device__ float g_prm1[512];
__device__ float g_prm2[512];
__device__ float g_pool[BB * HC];

// ---------------- zero scratch ----------------
__global__ void k_zero() {
    int stride = gridDim.x * blockDim.x;
    int i = blockIdx.x * blockDim.x + threadIdx.x;
    for (int j = i; j < NN; j += stride) g_deg[j] = 0;
    for (int j = i; j < BB; j += stride) g_counts[j] = 0;
    for (int j = i; j < 512; j += stride) { g_bn1[j] = 0.f; g_bn2[j] = 0.f; }
    for (int j = i; j < BB * HC; j += stride) g_pool[j] = 0.f;
}

// ---------------- graph counts ----------------
__global__ void k_counts(const int* __restrict__ batch) {
    __shared__ int sm[BB];
    int t = threadIdx.x;
    if (t < BB) sm[t] = 0;
    __syncthreads();
    int i = blockIdx.x * blockDim.x + t;
    if (i < NN) atomicAdd(&sm[batch[i]], 1);
    __syncthreads();
    if (t < BB && sm[t]) atomicAdd(&g_counts[t], sm[t]);
}

__global__ void k_graph_meta() {
    if (threadIdx.x == 0 && blockIdx.x == 0) {
        int acc = 0;
        for (int b = 0; b < BB; b++) {
            int c = g_counts[b];
            g_starts[b] = acc;
            acc += c;
            g_gs[b] = (int)ceilf(sqrtf((float)c));
        }
    }
}

// ---------------- CSR build ----------------
__global__ void k_degree(const int* __restrict__ ei) {
    int e = blockIdx.x * blockDim.x + threadIdx.x;
    if (e >= ETOT) return;
    int d = (e < EE) ? ei[EE + e] : (e - EE);
    atomicAdd(&g_deg[d], 1);
}

__global__ void k_scan_deg() {
    __shared__ int sm[1024];
    __shared__ int s_carry;
    int t = threadIdx.x;
    if (t == 0) s_carry = 0;
    __syncthreads();
    for (int base = 0; base < NN; base += 1024) {
        int i = base + t;
        int v = (i < NN) ? g_deg[i] : 0;
        sm[t] = v;
        __syncthreads();
        #pragma unroll
        for (int off = 1; off < 1024; off <<= 1) {
            int xv = (t >= off) ? sm[t - off] : 0;
            __syncthreads();
            sm[t] += xv;
            __syncthreads();
        }
        int carry = s_carry;
        int excl = carry + sm[t] - v;
        if (i < NN) { g_off[i] = excl; g_cur[i] = excl; }
        __syncthreads();
        if (t == 0) s_carry = carry + sm[1023];
        __syncthreads();
    }
    if (t == 0) g_off[NN] = s_carry;
}

__global__ void k_scatter(const int* __restrict__ ei) {
    int e = blockIdx.x * blockDim.x + threadIdx.x;
    if (e >= ETOT) return;
    int s, d;
    if (e < EE) { s = ei[e]; d = ei[EE + e]; }
    else { s = d = e - EE; }
    int p = atomicAdd(&g_cur[d], 1);
    g_csr[p] = s;
}

// ---------------- tensor-core GEMM (tf32): C[M,256] = A[M,K] @ B[K,256] ----
template <int K, bool FUSE_PE>
__global__ void k_gemm_tc(const float* __restrict__ A, const float* __restrict__ Bw,
                          float* __restrict__ C, int M,
                          const float* __restrict__ x, const int* __restrict__ batch,
                          const float* __restrict__ Wpos, const float* __restrict__ bpos) {
    const int BM = 128, BN = 64, BK = 32;
    const int LDA = BK + 4;   // 36
    const int LDB = BN + 4;   // 68
    __shared__ float sm[BM * LDB];          // 8704 floats, reused for staging
    float* As = sm;                          // [BM][LDA]
    float* Bs = sm + BM * LDA;               // [BK][LDB]

    int tid = threadIdx.x;
    int warp = tid >> 5;
    int wm = warp & 3;
    int wn = warp >> 2;
    int row0 = blockIdx.x * BM;
    int col0 = blockIdx.y * BN;

    wmma::fragment<wmma::accumulator, 16, 16, 8, float> acc[2][2];
    #pragma unroll
    for (int i = 0; i < 2; i++)
        #pragma unroll
        for (int j = 0; j < 2; j++) wmma::fill_fragment(acc[i][j], 0.f);

    for (int k0 = 0; k0 < K; k0 += BK) {
        if (!FUSE_PE || k0 < F_IN) {
            int r = tid >> 1;
            int cbase = (tid & 1) * 16;
            int gr = row0 + r;
            const float* src = FUSE_PE ? (x + (size_t)gr * F_IN + k0 + cbase)
                                       : (A + (size_t)gr * K + k0 + cbase);
            #pragma unroll
            for (int v = 0; v < 4; v++) {
                float4 val = make_float4(0.f, 0.f, 0.f, 0.f);
                if (gr < M) val = *(const float4*)(src + v * 4);
                float* d = &As[r * LDA + cbase + v * 4];
                d[0] = wmma::__float_to_tf32(val.x);
                d[1] = wmma::__float_to_tf32(val.y);
                d[2] = wmma::__float_to_tf32(val.z);
                d[3] = wmma::__float_to_tf32(val.w);
            }
        } else {
            int r = tid >> 1;
            int half = tid & 1;
            int gr = row0 + r;
            if (half == 0) {
                float p0 = 0.f, p1 = 0.f;
                if (gr < M) {
                    int b = batch[gr];
                    int g = g_gs[b];
                    int i = gr - g_starts[b];
                    int rowI = i / g;
                    int colI = i - rowI * g;
                    float denom = (float)(g - 1 > 1 ? g - 1 : 1);
                    p0 = (float)rowI / denom;
                    p1 = (float)colI / denom;
                }
                #pragma unroll
                for (int jj = 0; jj < 16; jj++) {
                    float v = (gr < M) ? (p0 * Wpos[jj] + p1 * Wpos[POS + jj] + bpos[jj]) : 0.f;
                    As[r * LDA + jj] = wmma::__float_to_tf32(v);
                }
            } else {
                #pragma unroll
                for (int jj = 0; jj < 16; jj++) As[r * LDA + 16 + jj] = 0.f;
            }
        }
        {
            int idx = tid * 8;
            int kk = idx >> 6;
            int cc = idx & 63;
            #pragma unroll
            for (int v = 0; v < 2; v++) {
                float4 val = make_float4(0.f, 0.f, 0.f, 0.f);
                if (k0 + kk < K) val = *(const float4*)&Bw[(size_t)(k0 + kk) * HC + col0 + cc + v * 4];
                float* d = &Bs[kk * LDB + cc + v * 4];
                d[0] = wmma::__float_to_tf32(val.x);
                d[1] = wmma::__float_to_tf32(val.y);
                d[2] = wmma::__float_to_tf32(val.z);
                d[3] = wmma::__float_to_tf32(val.w);
            }
        }
        __syncthreads();
        #pragma unroll
        for (int ks = 0; ks < BK; ks += 8) {
            wmma::fragment<wmma::matrix_a, 16, 16, 8, wmma::precision::tf32, wmma::row_major> af[2];
            wmma::fragment<wmma::matrix_b, 16, 16, 8, wmma::precision::tf32, wmma::row_major> bf[2];
            #pragma unroll
            for (int i = 0; i < 2; i++)
                wmma::load_matrix_sync(af[i], &As[(wm * 32 + i * 16) * LDA + ks], LDA);
            #pragma unroll
            for (int j = 0; j < 2; j++)
                wmma::load_matrix_sync(bf[j], &Bs[ks * LDB + wn * 32 + j * 16], LDB);
            #pragma unroll
            for (int i = 0; i < 2; i++)
                #pragma unroll
                for (int j = 0; j < 2; j++)
                    wmma::mma_sync(acc[i][j], af[i], bf[j], acc[i][j]);
        }
        __syncthreads();
    }

    if (row0 + BM <= M) {
        #pragma unroll
        for (int i = 0; i < 2; i++)
            #pragma unroll
            for (int j = 0; j < 2; j++)
                wmma::store_matrix_sync(&C[(size_t)(row0 + wm * 32 + i * 16) * HC + col0 + wn * 32 + j * 16],
                                        acc[i][j], HC, wmma::mem_row_major);
    } else {
        #pragma unroll
        for (int i = 0; i < 2; i++)
            #pragma unroll
            for (int j = 0; j < 2; j++)
                wmma::store_matrix_sync(&sm[(wm * 32 + i * 16) * LDB + wn * 32 + j * 16],
                                        acc[i][j], LDB, wmma::mem_row_major);
        __syncthreads();
        for (int e = tid; e < BM * BN; e += 256) {
            int r = e >> 6;
            int c = e & 63;
            int gr = row0 + r;
            if (gr < M) C[(size_t)gr * HC + col0 + c] = sm[r * LDB + c];
        }
    }
}

// ---------------- attention coefficients ----------------
__global__ void k_attn(const float* __restrict__ h, const float* __restrict__ a_src,
                       const float* __restrict__ a_dst) {
    int gw = (blockIdx.x * blockDim.x + threadIdx.x) >> 5;
    int lane = threadIdx.x & 31;
    if (gw >= NN) return;
    const float* row = h + (size_t)gw * HC;
    float ps[4] = {0, 0, 0, 0}, pd[4] = {0, 0, 0, 0};
    #pragma unroll
    for (int k = 0; k < 8; k++) {
        int ch = lane + 32 * k;
        int hd = k >> 1;
        float v = row[ch];
        ps[hd] += v * a_src[ch];
        pd[hd] += v * a_dst[ch];
    }
    #pragma unroll
    for (int hd = 0; hd < 4; hd++) {
        #pragma unroll
        for (int off = 16; off; off >>= 1) {
            ps[hd] += __shfl_xor_sync(0xFFFFFFFFu, ps[hd], off);
            pd[hd] += __shfl_xor_sync(0xFFFFFFFFu, pd[hd], off);
        }
    }
    if (lane < 4) {
        g_as[gw * 4 + lane] = ps[lane];
        g_ad[gw * 4 + lane] = pd[lane];
    }
}

// ---------------- softmax-aggregate (warp per node) + fused BN stats ----------------
__global__ void k_agg(const float* __restrict__ h, const float* __restrict__ bias,
                      float* __restrict__ out, float* __restrict__ bnsums) {
    int tid = threadIdx.x;
    int wp = tid >> 5;
    int lane = tid & 31;
    int node = blockIdx.x * 8 + wp;
    __shared__ float wsm[8][32][4];
    __shared__ float ssum[HC];
    __shared__ float ssum2[HC];
    ssum[tid] = 0.f;
    ssum2[tid] = 0.f;
    __syncthreads();

    int beg = g_off[node], end = g_off[node + 1];
    float ad0 = g_ad[node * 4 + 0], ad1 = g_ad[node * 4 + 1];
    float ad2 = g_ad[node * 4 + 2], ad3 = g_ad[node * 4 + 3];

    float m0 = -1e30f, m1 = -1e30f, m2 = -1e30f, m3 = -1e30f;
    for (int j = beg + lane; j < end; j += 32) {
        int s = g_csr[j];
        const float* as = &g_as[s * 4];
        float v0 = as[0] + ad0; v0 = v0 > 0.f ? v0 : 0.2f * v0; m0 = fmaxf(m0, v0);
        float v1 = as[1] + ad1; v1 = v1 > 0.f ? v1 : 0.2f * v1; m1 = fmaxf(m1, v1);
        float v2 = as[2] + ad2; v2 = v2 > 0.f ? v2 : 0.2f * v2; m2 = fmaxf(m2, v2);
        float v3 = as[3] + ad3; v3 = v3 > 0.f ? v3 : 0.2f * v3; m3 = fmaxf(m3, v3);
    }
    #pragma unroll
    for (int off = 16; off; off >>= 1) {
        m0 = fmaxf(m0, __shfl_xor_sync(0xFFFFFFFFu, m0, off));
        m1 = fmaxf(m1, __shfl_xor_sync(0xFFFFFFFFu, m1, off));
        m2 = fmaxf(m2, __shfl_xor_sync(0xFFFFFFFFu, m2, off));
        m3 = fmaxf(m3, __shfl_xor_sync(0xFFFFFFFFu, m3, off));
    }

    float acc[8] = {0, 0, 0, 0, 0, 0, 0, 0};
    float sw0 = 0.f, sw1 = 0.f, sw2 = 0.f, sw3 = 0.f;
    for (int base = beg; base < end; base += 32) {
        int j = base + lane;
        float w0 = 0.f, w1 = 0.f, w2 = 0.f, w3 = 0.f;
        if (j < end) {
            int s = g_csr[j];
            const float* as = &g_as[s * 4];
            float v0 = as[0] + ad0; v0 = v0 > 0.f ? v0 : 0.2f * v0; w0 = __expf(v0 - m0);
            float v1 = as[1] + ad1; v1 = v1 > 0.f ? v1 : 0.2f * v1; w1 = __expf(v1 - m1);
            float v2 = as[2] + ad2; v2 = v2 > 0.f ? v2 : 0.2f * v2; w2 = __expf(v2 - m2);
            float v3 = as[3] + ad3; v3 = v3 > 0.f ? v3 : 0.2f * v3; w3 = __expf(v3 - m3);
        }
        wsm[wp][lane][0] = w0; wsm[wp][lane][1] = w1;
        wsm[wp][lane][2] = w2; wsm[wp][lane][3] = w3;
        sw0 += w0; sw1 += w1; sw2 += w2; sw3 += w3;
        __syncwarp();
        int cnt = end - base; if (cnt > 32) cnt = 32;
        for (int t = 0; t < cnt; t++) {
            int ss = g_csr[base + t];
            float wv0 = wsm[wp][t][0], wv1 = wsm[wp][t][1];
            float wv2 = wsm[wp][t][2], wv3 = wsm[wp][t][3];
            const float* hp = &h[(size_t)ss * HC + lane];
            acc[0] += wv0 * hp[0];   acc[1] += wv0 * hp[32];
            acc[2] += wv1 * hp[64];  acc[3] += wv1 * hp[96];
            acc[4] += wv2 * hp[128]; acc[5] += wv2 * hp[160];
            acc[6] += wv3 * hp[192]; acc[7] += wv3 * hp[224];
        }
        __syncwarp();
    }
    #pragma unroll
    for (int off = 16; off; off >>= 1) {
        sw0 += __shfl_xor_sync(0xFFFFFFFFu, sw0, off);
        sw1 += __shfl_xor_sync(0xFFFFFFFFu, sw1, off);
        sw2 += __shfl_xor_sync(0xFFFFFFFFu, sw2, off);
        sw3 += __shfl_xor_sync(0xFFFFFFFFu, sw3, off);
    }
    float i0 = 1.f / sw0, i1 = 1.f / sw1, i2 = 1.f / sw2, i3 = 1.f / sw3;
    float res[8];
    res[0] = acc[0] * i0 + bias[lane];
    res[1] = acc[1] * i0 + bias[lane + 32];
    res[2] = acc[2] * i1 + bias[lane + 64];
    res[3] = acc[3] * i1 + bias[lane + 96];
    res[4] = acc[4] * i2 + bias[lane + 128];
    res[5] = acc[5] * i2 + bias[lane + 160];
    res[6] = acc[6] * i3 + bias[lane + 192];
    res[7] = acc[7] * i3 + bias[lane + 224];
    float* op = &out[(size_t)node * HC + lane];
    #pragma unroll
    for (int k = 0; k < 8; k++) {
        op[32 * k] = res[k];
        atomicAdd(&ssum[lane + 32 * k], res[k]);
        atomicAdd(&ssum2[lane + 32 * k], res[k] * res[k]);
    }
    __syncthreads();
    atomicAdd(&bnsums[tid], ssum[tid]);
    atomicAdd(&bnsums[HC + tid], ssum2[tid]);
}

// ---------------- batch norm finalize + fused BN+ELU ----------------
__global__ void k_bn_fin(const float* __restrict__ sums, const float* __restrict__ gamma,
                         const float* __restrict__ beta, float* __restrict__ prm) {
    int ch = threadIdx.x;
    float mean = sums[ch] / (float)NN;
    float var = sums[HC + ch] / (float)NN - mean * mean;
    float inv = rsqrtf(var + 1e-5f);
    float sc = gamma[ch] * inv;
    prm[ch] = sc;
    prm[HC + ch] = beta[ch] - mean * sc;
}

__global__ void k_bn_elu(float* __restrict__ x, const float* __restrict__ prm) {
    long idx = (long)blockIdx.x * blockDim.x + threadIdx.x;
    if (idx >= (long)NN * HC) return;
    int ch = (int)(idx & (HC - 1));
    float v = x[idx] * prm[ch] + prm[HC + ch];
    x[idx] = v > 0.f ? v : (__expf(v) - 1.f);
}

// ---------------- pooling + FC ----------------
__global__ void k_pool(const float* __restrict__ x) {
    int g = blockIdx.x, part = blockIdx.y, ch = threadIdx.x;
    int beg = g_starts[g], cnt = g_counts[g];
    float s = 0.f;
    for (int r = part; r < cnt; r += 8)
        s += x[(size_t)(beg + r) * HC + ch];
    atomicAdd(&g_pool[g * HC + ch], s);
}

__global__ void k_fc(const float* __restrict__ Wfc, const float* __restrict__ bfc,
                     float* __restrict__ out) {
    int g = blockIdx.x, o = threadIdx.x;
    __shared__ float ps[HC];
    float invc = 1.f / (float)g_counts[g];
    for (int c = o; c < HC; c += OUT_DIM) ps[c] = g_pool[g * HC + c] * invc;
    __syncthreads();
    float acc = bfc[o];
    #pragma unroll 8
    for (int c = 0; c < HC; c++) acc += ps[c] * Wfc[c * OUT_DIM + o];
    out[g * OUT_DIM + o] = acc;
}

// ---------------- launch ----------------
extern "C" void kernel_launch(void* const* d_in, const int* in_sizes, int n_in,
                              void* d_out, int out_size) {
    const float* x       = (const float*)d_in[0];
    const int*   ei      = (const int*)d_in[1];
    const int*   batch   = (const int*)d_in[2];
    const float* W_pos   = (const float*)d_in[3];
    const float* b_pos   = (const float*)d_in[4];
    const float* W1      = (const float*)d_in[5];
    const float* a_src1  = (const float*)d_in[6];
    const float* a_dst1  = (const float*)d_in[7];
    const float* b1      = (const float*)d_in[8];
    const float* gamma1  = (const float*)d_in[9];
    const float* beta1   = (const float*)d_in[10];
    const float* W2      = (const float*)d_in[11];
    const float* a_src2  = (const float*)d_in[12];
    const float* a_dst2  = (const float*)d_in[13];
    const float* b2      = (const float*)d_in[14];
    const float* gamma2  = (const float*)d_in[15];
    const float* beta2   = (const float*)d_in[16];
    const float* W_fc    = (const float*)d_in[17];
    const float* b_fc    = (const float*)d_in[18];
    float* out = (float*)d_out;

    float *hA, *hB, *bn1, *bn2, *prm1, *prm2;
    cudaGetSymbolAddress((void**)&hA, g_hA);
    cudaGetSymbolAddress((void**)&hB, g_hB);
    cudaGetSymbolAddress((void**)&bn1, g_bn1);
    cudaGetSymbolAddress((void**)&bn2, g_bn2);
    cudaGetSymbolAddress((void**)&prm1, g_prm1);
    cudaGetSymbolAddress((void**)&prm2, g_prm2);

    // setup
    k_zero<<<256, 256>>>();
    k_counts<<<(NN + 255) / 256, 256>>>(batch);
    k_graph_meta<<<1, 32>>>();
    k_degree<<<(ETOT + 255) / 256, 256>>>(ei);
    k_scan_deg<<<1, 1024>>>();
    k_scatter<<<(ETOT + 255) / 256, 256>>>(ei);

    // layer 1 (PE fused into GEMM A-load):  hA = GEMM(concat(x,PE), W1)
    dim3 gg((NN + 127) / 128, HC / 64);
    k_gemm_tc<ENH, true><<<gg, 256>>>(nullptr, W1, hA, NN, x, batch, W_pos, b_pos);
    k_attn<<<(NN * 32 + 255) / 256, 256>>>(hA, a_src1, a_dst1);
    k_agg<<<NN / 8, 256>>>(hA, b1, hB, bn1);          // hB = GAT1 out (+BN stats)
    k_bn_fin<<<1, 256>>>(bn1, gamma1, beta1, prm1);
    k_bn_elu<<<(int)(((long)NN * HC + 255) / 256), 256>>>(hB, prm1);

    // layer 2:  hA = GEMM(hB, W2); hB2 -> reuse hA? no: agg writes hB... use hA as gemm out,
    // agg reads hA and writes hB (hB's old contents no longer needed after GEMM).
    k_gemm_tc<HC, false><<<gg, 256>>>(hB, W2, hA, NN, nullptr, nullptr, nullptr, nullptr);
    k_attn<<<(NN * 32 + 255) / 256, 256>>>(hA, a_src2, a_dst2);
    k_agg<<<NN / 8, 256>>>(hA, b2, hB, bn2);          // hB = GAT2 out (+BN stats)
    k_bn_fin<<<1, 256>>>(bn2, gamma2, beta2, prm2);
    k_bn_elu<<<(int)(((long)NN * HC + 255) / 256), 256>>>(hB, prm2);

    // pool + fc
    dim3 gp(BB, 8);
    k_pool<<<gp, 256>>>(hB);
    k_fc<<<BB, OUT_DIM>>>(W_fc, b_fc, out);
}

// round 4
// speedup vs baseline: 1.4939x; 1.1619x over previous
#include <cuda_runtime.h>
#include <math.h>
#include <mma.h>

using namespace nvcuda;

#define NN 50000
#define EE 800000
#define ETOT (EE + NN)
#define BB 64
#define F_IN 128
#define POS 16
#define ENH 144
#define HC 256
#define OUT_DIM 128
#define SCAN_B 1024
#define NBLK ((NN + SCAN_B - 1) / SCAN_B)   // 49

// ---------------- scratch (device globals; no allocation allowed) ----------------
__device__ float g_hA[(size_t)NN * HC];
__device__ float g_hB[(size_t)NN * HC];
__device__ float g_as[NN * 4];
__device__ float g_ad[NN * 4];
__device__ int   g_deg[NN];
__device__ int   g_off[NN + 1];
__device__ int   g_cur[NN];
__device__ int   g_csr[ETOT];
__device__ int   g_bsum[NBLK];
__device__ int   g_counts[BB];
__device__ int   g_starts[BB];
__device__ int   g_gs[BB];
__device__ float g_bn1[512];
__device__ float g_bn2[512];
__device__ float g_prm1[512];
__device__ float g_prm2[512];
__device__ float g_pool[BB * HC];

// ---------------- zero scratch ----------------
__global__ void k_zero() {
    int stride = gridDim.x * blockDim.x;
    int i = blockIdx.x * blockDim.x + threadIdx.x;
    for (int j = i; j < NN; j += stride) g_deg[j] = 0;
    for (int j = i; j < BB; j += stride) g_counts[j] = 0;
    for (int j = i; j < 512; j += stride) { g_bn1[j] = 0.f; g_bn2[j] = 0.f; }
    for (int j = i; j < BB * HC; j += stride) g_pool[j] = 0.f;
}

// ---------------- graph counts ----------------
__global__ void k_counts(const int* __restrict__ batch) {
    __shared__ int sm[BB];
    int t = threadIdx.x;
    if (t < BB) sm[t] = 0;
    __syncthreads();
    int i = blockIdx.x * blockDim.x + t;
    if (i < NN) atomicAdd(&sm[batch[i]], 1);
    __syncthreads();
    if (t < BB && sm[t]) atomicAdd(&g_counts[t], sm[t]);
}

__global__ void k_graph_meta() {
    if (threadIdx.x == 0 && blockIdx.x == 0) {
        int acc = 0;
        for (int b = 0; b < BB; b++) {
            int c = g_counts[b];
            g_starts[b] = acc;
            acc += c;
            g_gs[b] = (int)ceilf(sqrtf((float)c));
        }
    }
}

// ---------------- CSR build ----------------
__global__ void k_degree(const int* __restrict__ ei) {
    int e = blockIdx.x * blockDim.x + threadIdx.x;
    if (e >= ETOT) return;
    int d = (e < EE) ? ei[EE + e] : (e - EE);
    atomicAdd(&g_deg[d], 1);
}

// phase 1: per-tile inclusive scan (49 blocks in parallel)
__global__ void k_scan1() {
    __shared__ int sm[SCAN_B];
    int t = threadIdx.x;
    int i = blockIdx.x * SCAN_B + t;
    int v = (i < NN) ? g_deg[i] : 0;
    sm[t] = v;
    __syncthreads();
    #pragma unroll
    for (int off = 1; off < SCAN_B; off <<= 1) {
        int xv = (t >= off) ? sm[t - off] : 0;
        __syncthreads();
        sm[t] += xv;
        __syncthreads();
    }
    if (i < NN) g_off[i] = sm[t];               // inclusive, tile-local
    if (t == SCAN_B - 1) g_bsum[blockIdx.x] = sm[t];
}

// phase 2: serial exclusive scan of 49 tile totals
__global__ void k_scan2() {
    if (threadIdx.x == 0) {
        int run = 0;
        for (int b = 0; b < NBLK; b++) {
            int t = g_bsum[b];
            g_bsum[b] = run;
            run += t;
        }
        g_off[NN] = run;    // == ETOT
    }
}

// phase 3: convert to global exclusive offsets
__global__ void k_scan3() {
    int i = blockIdx.x * blockDim.x + threadIdx.x;
    if (i >= NN) return;
    int e = g_off[i] - g_deg[i] + g_bsum[i / SCAN_B];
    g_off[i] = e;
    g_cur[i] = e;
}

__global__ void k_scatter(const int* __restrict__ ei) {
    int e = blockIdx.x * blockDim.x + threadIdx.x;
    if (e >= ETOT) return;
    int s, d;
    if (e < EE) { s = ei[e]; d = ei[EE + e]; }
    else { s = d = e - EE; }
    int p = atomicAdd(&g_cur[d], 1);
    g_csr[p] = s;
}

// ---------------- tensor-core GEMM (tf32) + fused attn coefficients ----------------
// C[M,256] = A[M,K] @ B[K,256].  BN=64 == head width -> blockIdx.y == head.
template <int K, bool FUSE_PE>
__global__ void k_gemm_tc(const float* __restrict__ A, const float* __restrict__ Bw,
                          float* __restrict__ C, int M,
                          const float* __restrict__ x, const int* __restrict__ batch,
                          const float* __restrict__ Wpos, const float* __restrict__ bpos,
                          const float* __restrict__ a_src, const float* __restrict__ a_dst) {
    const int BM = 128, BN = 64, BK = 32;
    const int LDA = BK + 4;   // 36
    const int LDB = BN + 4;   // 68
    __shared__ float sm[BM * LDB];          // 8704 floats; As+Bs in mainloop, C tile in epilogue
    float* As = sm;                          // [BM][LDA]
    float* Bs = sm + BM * LDA;               // [BK][LDB]

    int tid = threadIdx.x;
    int warp = tid >> 5;
    int wm = warp & 3;
    int wn = warp >> 2;
    int row0 = blockIdx.x * BM;
    int col0 = blockIdx.y * BN;

    wmma::fragment<wmma::accumulator, 16, 16, 8, float> acc[2][2];
    #pragma unroll
    for (int i = 0; i < 2; i++)
        #pragma unroll
        for (int j = 0; j < 2; j++) wmma::fill_fragment(acc[i][j], 0.f);

    for (int k0 = 0; k0 < K; k0 += BK) {
        if (!FUSE_PE || k0 < F_IN) {
            int r = tid >> 1;
            int cbase = (tid & 1) * 16;
            int gr = row0 + r;
            const float* src = FUSE_PE ? (x + (size_t)gr * F_IN + k0 + cbase)
                                       : (A + (size_t)gr * K + k0 + cbase);
            #pragma unroll
            for (int v = 0; v < 4; v++) {
                float4 val = make_float4(0.f, 0.f, 0.f, 0.f);
                if (gr < M) val = *(const float4*)(src + v * 4);
                float* d = &As[r * LDA + cbase + v * 4];
                d[0] = wmma::__float_to_tf32(val.x);
                d[1] = wmma::__float_to_tf32(val.y);
                d[2] = wmma::__float_to_tf32(val.z);
                d[3] = wmma::__float_to_tf32(val.w);
            }
        } else {
            int r = tid >> 1;
            int half = tid & 1;
            int gr = row0 + r;
            if (half == 0) {
                float p0 = 0.f, p1 = 0.f;
                if (gr < M) {
                    int b = batch[gr];
                    int g = g_gs[b];
                    int i = gr - g_starts[b];
                    int rowI = i / g;
                    int colI = i - rowI * g;
                    float denom = (float)(g - 1 > 1 ? g - 1 : 1);
                    p0 = (float)rowI / denom;
                    p1 = (float)colI / denom;
                }
                #pragma unroll
                for (int jj = 0; jj < 16; jj++) {
                    float v = (gr < M) ? (p0 * Wpos[jj] + p1 * Wpos[POS + jj] + bpos[jj]) : 0.f;
                    As[r * LDA + jj] = wmma::__float_to_tf32(v);
                }
            } else {
                #pragma unroll
                for (int jj = 0; jj < 16; jj++) As[r * LDA + 16 + jj] = 0.f;
            }
        }
        {
            int idx = tid * 8;
            int kk = idx >> 6;
            int cc = idx & 63;
            #pragma unroll
            for (int v = 0; v < 2; v++) {
                float4 val = make_float4(0.f, 0.f, 0.f, 0.f);
                if (k0 + kk < K) val = *(const float4*)&Bw[(size_t)(k0 + kk) * HC + col0 + cc + v * 4];
                float* d = &Bs[kk * LDB + cc + v * 4];
                d[0] = wmma::__float_to_tf32(val.x);
                d[1] = wmma::__float_to_tf32(val.y);
                d[2] = wmma::__float_to_tf32(val.z);
                d[3] = wmma::__float_to_tf32(val.w);
            }
        }
        __syncthreads();
        #pragma unroll
        for (int ks = 0; ks < BK; ks += 8) {
            wmma::fragment<wmma::matrix_a, 16, 16, 8, wmma::precision::tf32, wmma::row_major> af[2];
            wmma::fragment<wmma::matrix_b, 16, 16, 8, wmma::precision::tf32, wmma::row_major> bf[2];
            #pragma unroll
            for (int i = 0; i < 2; i++)
                wmma::load_matrix_sync(af[i], &As[(wm * 32 + i * 16) * LDA + ks], LDA);
            #pragma unroll
            for (int j = 0; j < 2; j++)
                wmma::load_matrix_sync(bf[j], &Bs[ks * LDB + wn * 32 + j * 16], LDB);
            #pragma unroll
            for (int i = 0; i < 2; i++)
                #pragma unroll
                for (int j = 0; j < 2; j++)
                    wmma::mma_sync(acc[i][j], af[i], bf[j], acc[i][j]);
        }
        __syncthreads();
    }

    // ---- epilogue: stage C tile in smem, write out, compute attn coefficients ----
    #pragma unroll
    for (int i = 0; i < 2; i++)
        #pragma unroll
        for (int j = 0; j < 2; j++)
            wmma::store_matrix_sync(&sm[(wm * 32 + i * 16) * LDB + wn * 32 + j * 16],
                                    acc[i][j], LDB, wmma::mem_row_major);
    __syncthreads();

    // vectorized copy to C
    for (int e = tid; e < BM * BN / 4; e += 256) {
        int r = e >> 4;            // 16 float4 per row
        int c = (e & 15) * 4;
        int gr = row0 + r;
        if (gr < M) *(float4*)&C[(size_t)gr * HC + col0 + c] = *(float4*)&sm[r * LDB + c];
    }

    // attn coefficients for this head (head = blockIdx.y; cols = full head channels)
    {
        int head = blockIdx.y;
        int r = tid >> 1;
        int halfc = (tid & 1) * 32;
        int gr = row0 + r;
        const float* av = a_src + head * 64;
        const float* dv = a_dst + head * 64;
        float ps = 0.f, pd = 0.f;
        #pragma unroll 8
        for (int k = 0; k < 32; k++) {
            float v = sm[r * LDB + halfc + k];
            ps += v * av[halfc + k];
            pd += v * dv[halfc + k];
        }
        ps += __shfl_xor_sync(0xFFFFFFFFu, ps, 1);
        pd += __shfl_xor_sync(0xFFFFFFFFu, pd, 1);
        if ((tid & 1) == 0 && gr < M) {
            g_as[gr * 4 + head] = ps;
            g_ad[gr * 4 + head] = pd;
        }
    }
}

// ---------------- softmax-aggregate (warp per node) + fused BN stats ----------------
__global__ void k_agg(const float* __restrict__ h, const float* __restrict__ bias,
                      float* __restrict__ out, float* __restrict__ bnsums) {
    int tid = threadIdx.x;
    int wp = tid >> 5;
    int lane = tid & 31;
    int node = blockIdx.x * 8 + wp;
    __shared__ float wsm[8][32][4];
    __shared__ float ssum[HC];
    __shared__ float ssum2[HC];
    ssum[tid] = 0.f;
    ssum2[tid] = 0.f;
    __syncthreads();

    int beg = g_off[node], end = g_off[node + 1];
    float ad0 = g_ad[node * 4 + 0], ad1 = g_ad[node * 4 + 1];
    float ad2 = g_ad[node * 4 + 2], ad3 = g_ad[node * 4 + 3];

    float m0 = -1e30f, m1 = -1e30f, m2 = -1e30f, m3 = -1e30f;
    for (int j = beg + lane; j < end; j += 32) {
        int s = g_csr[j];
        const float* as = &g_as[s * 4];
        float v0 = as[0] + ad0; v0 = v0 > 0.f ? v0 : 0.2f * v0; m0 = fmaxf(m0, v0);
        float v1 = as[1] + ad1; v1 = v1 > 0.f ? v1 : 0.2f * v1; m1 = fmaxf(m1, v1);
        float v2 = as[2] + ad2; v2 = v2 > 0.f ? v2 : 0.2f * v2; m2 = fmaxf(m2, v2);
        float v3 = as[3] + ad3; v3 = v3 > 0.f ? v3 : 0.2f * v3; m3 = fmaxf(m3, v3);
    }
    #pragma unroll
    for (int off = 16; off; off >>= 1) {
        m0 = fmaxf(m0, __shfl_xor_sync(0xFFFFFFFFu, m0, off));
        m1 = fmaxf(m1, __shfl_xor_sync(0xFFFFFFFFu, m1, off));
        m2 = fmaxf(m2, __shfl_xor_sync(0xFFFFFFFFu, m2, off));
        m3 = fmaxf(m3, __shfl_xor_sync(0xFFFFFFFFu, m3, off));
    }

    float acc[8] = {0, 0, 0, 0, 0, 0, 0, 0};
    float sw0 = 0.f, sw1 = 0.f, sw2 = 0.f, sw3 = 0.f;
    for (int base = beg; base < end; base += 32) {
        int j = base + lane;
        float w0 = 0.f, w1 = 0.f, w2 = 0.f, w3 = 0.f;
        if (j < end) {
            int s = g_csr[j];
            const float* as = &g_as[s * 4];
            float v0 = as[0] + ad0; v0 = v0 > 0.f ? v0 : 0.2f * v0; w0 = __expf(v0 - m0);
            float v1 = as[1] + ad1; v1 = v1 > 0.f ? v1 : 0.2f * v1; w1 = __expf(v1 - m1);
            float v2 = as[2] + ad2; v2 = v2 > 0.f ? v2 : 0.2f * v2; w2 = __expf(v2 - m2);
            float v3 = as[3] + ad3; v3 = v3 > 0.f ? v3 : 0.2f * v3; w3 = __expf(v3 - m3);
        }
        wsm[wp][lane][0] = w0; wsm[wp][lane][1] = w1;
        wsm[wp][lane][2] = w2; wsm[wp][lane][3] = w3;
        sw0 += w0; sw1 += w1; sw2 += w2; sw3 += w3;
        __syncwarp();
        int cnt = end - base; if (cnt > 32) cnt = 32;
        for (int t = 0; t < cnt; t++) {
            int ss = g_csr[base + t];
            float wv0 = wsm[wp][t][0], wv1 = wsm[wp][t][1];
            float wv2 = wsm[wp][t][2], wv3 = wsm[wp][t][3];
            const float* hp = &h[(size_t)ss * HC + lane];
            acc[0] += wv0 * hp[0];   acc[1] += wv0 * hp[32];
            acc[2] += wv1 * hp[64];  acc[3] += wv1 * hp[96];
            acc[4] += wv2 * hp[128]; acc[5] += wv2 * hp[160];
            acc[6] += wv3 * hp[192]; acc[7] += wv3 * hp[224];
        }
        __syncwarp();
    }
    #pragma unroll
    for (int off = 16; off; off >>= 1) {
        sw0 += __shfl_xor_sync(0xFFFFFFFFu, sw0, off);
        sw1 += __shfl_xor_sync(0xFFFFFFFFu, sw1, off);
        sw2 += __shfl_xor_sync(0xFFFFFFFFu, sw2, off);
        sw3 += __shfl_xor_sync(0xFFFFFFFFu, sw3, off);
    }
    float i0 = 1.f / sw0, i1 = 1.f / sw1, i2 = 1.f / sw2, i3 = 1.f / sw3;
    float res[8];
    res[0] = acc[0] * i0 + bias[lane];
    res[1] = acc[1] * i0 + bias[lane + 32];
    res[2] = acc[2] * i1 + bias[lane + 64];
    res[3] = acc[3] * i1 + bias[lane + 96];
    res[4] = acc[4] * i2 + bias[lane + 128];
    res[5] = acc[5] * i2 + bias[lane + 160];
    res[6] = acc[6] * i3 + bias[lane + 192];
    res[7] = acc[7] * i3 + bias[lane + 224];
    float* op = &out[(size_t)node * HC + lane];
    #pragma unroll
    for (int k = 0; k < 8; k++) {
        op[32 * k] = res[k];
        atomicAdd(&ssum[lane + 32 * k], res[k]);
        atomicAdd(&ssum2[lane + 32 * k], res[k] * res[k]);
    }
    __syncthreads();
    atomicAdd(&bnsums[tid], ssum[tid]);
    atomicAdd(&bnsums[HC + tid], ssum2[tid]);
}

// ---------------- batch norm finalize ----------------
__global__ void k_bn_fin(const float* __restrict__ sums, const float* __restrict__ gamma,
                         const float* __restrict__ beta, float* __restrict__ prm) {
    int ch = threadIdx.x;
    float mean = sums[ch] / (float)NN;
    float var = sums[HC + ch] / (float)NN - mean * mean;
    float inv = rsqrtf(var + 1e-5f);
    float sc = gamma[ch] * inv;
    prm[ch] = sc;
    prm[HC + ch] = beta[ch] - mean * sc;
}

// BN+ELU in place (layer 1 output feeds GEMM2), float4-vectorized
__global__ void k_bn_elu(float* __restrict__ x, const float* __restrict__ prm) {
    long i4 = (long)blockIdx.x * blockDim.x + threadIdx.x;
    if (i4 >= (long)NN * HC / 4) return;
    int ch = (int)(i4 & (HC / 4 - 1)) * 4;
    float4 v = *(float4*)&x[i4 * 4];
    float4 s = *(const float4*)&prm[ch];
    float4 o = *(const float4*)&prm[HC + ch];
    v.x = v.x * s.x + o.x; v.x = v.x > 0.f ? v.x : (__expf(v.x) - 1.f);
    v.y = v.y * s.y + o.y; v.y = v.y > 0.f ? v.y : (__expf(v.y) - 1.f);
    v.z = v.z * s.z + o.z; v.z = v.z > 0.f ? v.z : (__expf(v.z) - 1.f);
    v.w = v.w * s.w + o.w; v.w = v.w > 0.f ? v.w : (__expf(v.w) - 1.f);
    *(float4*)&x[i4 * 4] = v;
}

// layer 2: BN+ELU fused directly into pooling (no activation writeback needed)
__global__ void k_bn_elu_pool(const float* __restrict__ x, const float* __restrict__ prm,
                              const int* __restrict__ batch) {
    int ch = threadIdx.x;                 // 0..255
    int r0 = blockIdx.x * 128;
    int rend = r0 + 128; if (rend > NN) rend = NN;
    float sc = prm[ch], of = prm[HC + ch];
    float acc = 0.f;
    int gcur = batch[r0];
    for (int r = r0; r < rend; r++) {
        int g = batch[r];                 // uniform across block -> broadcast load
        if (g != gcur) {
            atomicAdd(&g_pool[gcur * HC + ch], acc);
            acc = 0.f;
            gcur = g;
        }
        float v = x[(size_t)r * HC + ch] * sc + of;
        acc += (v > 0.f ? v : (__expf(v) - 1.f));
    }
    atomicAdd(&g_pool[gcur * HC + ch], acc);
}

__global__ void k_fc(const float* __restrict__ Wfc, const float* __restrict__ bfc,
                     float* __restrict__ out) {
    int g = blockIdx.x, o = threadIdx.x;
    __shared__ float ps[HC];
    float invc = 1.f / (float)g_counts[g];
    for (int c = o; c < HC; c += OUT_DIM) ps[c] = g_pool[g * HC + c] * invc;
    __syncthreads();
    float acc = bfc[o];
    #pragma unroll 8
    for (int c = 0; c < HC; c++) acc += ps[c] * Wfc[c * OUT_DIM + o];
    out[g * OUT_DIM + o] = acc;
}

// ---------------- launch ----------------
extern "C" void kernel_launch(void* const* d_in, const int* in_sizes, int n_in,
                              void* d_out, int out_size) {
    const float* x       = (const float*)d_in[0];
    const int*   ei      = (const int*)d_in[1];
    const int*   batch   = (const int*)d_in[2];
    const float* W_pos   = (const float*)d_in[3];
    const float* b_pos   = (const float*)d_in[4];
    const float* W1      = (const float*)d_in[5];
    const float* a_src1  = (const float*)d_in[6];
    const float* a_dst1  = (const float*)d_in[7];
    const float* b1      = (const float*)d_in[8];
    const float* gamma1  = (const float*)d_in[9];
    const float* beta1   = (const float*)d_in[10];
    const float* W2      = (const float*)d_in[11];
    const float* a_src2  = (const float*)d_in[12];
    const float* a_dst2  = (const float*)d_in[13];
    const float* b2      = (const float*)d_in[14];
    const float* gamma2  = (const float*)d_in[15];
    const float* beta2   = (const float*)d_in[16];
    const float* W_fc    = (const float*)d_in[17];
    const float* b_fc    = (const float*)d_in[18];
    float* out = (float*)d_out;

    float *hA, *hB, *bn1, *bn2, *prm1, *prm2;
    cudaGetSymbolAddress((void**)&hA, g_hA);
    cudaGetSymbolAddress((void**)&hB, g_hB);
    cudaGetSymbolAddress((void**)&bn1, g_bn1);
    cudaGetSymbolAddress((void**)&bn2, g_bn2);
    cudaGetSymbolAddress((void**)&prm1, g_prm1);
    cudaGetSymbolAddress((void**)&prm2, g_prm2);

    // setup
    k_zero<<<256, 256>>>();
    k_counts<<<(NN + 255) / 256, 256>>>(batch);
    k_graph_meta<<<1, 32>>>();
    k_degree<<<(ETOT + 255) / 256, 256>>>(ei);
    k_scan1<<<NBLK, SCAN_B>>>();
    k_scan2<<<1, 32>>>();
    k_scan3<<<(NN + 255) / 256, 256>>>();
    k_scatter<<<(ETOT + 255) / 256, 256>>>(ei);

    dim3 gg((NN + 127) / 128, HC / 64);

    // layer 1 (PE + attn coefficients fused into GEMM)
    k_gemm_tc<ENH, true><<<gg, 256>>>(nullptr, W1, hA, NN, x, batch, W_pos, b_pos,
                                      a_src1, a_dst1);
    k_agg<<<NN / 8, 256>>>(hA, b1, hB, bn1);
    k_bn_fin<<<1, 256>>>(bn1, gamma1, beta1, prm1);
    k_bn_elu<<<(int)(((long)NN * HC / 4 + 255) / 256), 256>>>(hB, prm1);

    // layer 2 (attn fused into GEMM)
    k_gemm_tc<HC, false><<<gg, 256>>>(hB, W2, hA, NN, nullptr, nullptr, nullptr, nullptr,
                                      a_src2, a_dst2);
    k_agg<<<NN / 8, 256>>>(hA, b2, hB, bn2);
    k_bn_fin<<<1, 256>>>(bn2, gamma2, beta2, prm2);

    // fused BN+ELU+pool (layer-2 activations never written back)
    k_bn_elu_pool<<<(NN + 127) / 128, 256>>>(hB, prm2, batch);
    k_fc<<<BB, OUT_DIM>>>(W_fc, b_fc, out);
}

// round 6
// speedup vs baseline: 1.5855x; 1.0613x over previous
#include <cuda_runtime.h>
#include <cuda_fp16.h>
#include <math.h>
#include <mma.h>

using namespace nvcuda;

#define NN 50000
#define EE 800000
#define ETOT (EE + NN)
#define BB 64
#define F_IN 128
#define POS 16
#define ENH 144
#define HC 256
#define OUT_DIM 128
#define SCAN_B 1024
#define NBLK ((NN + SCAN_B - 1) / SCAN_B)   // 49

// ---------------- scratch (device globals; no allocation allowed) ----------------
__device__ __half g_hH[(size_t)NN * HC];    // GEMM output (feeds aggregation only)
__device__ float  g_hF[(size_t)NN * HC];    // agg output / BN / GEMM2 input
__device__ float g_as[NN * 4];
__device__ float g_ad[NN * 4];
__device__ int   g_deg[NN];
__device__ int   g_off[NN + 1];
__device__ int   g_cur[NN];
__device__ int   g_csr[ETOT];
__device__ int   g_bsum[NBLK];
__device__ int   g_counts[BB];
__device__ int   g_starts[BB];
__device__ int   g_gs[BB];
__device__ float g_bn1[512];
__device__ float g_bn2[512];
__device__ float g_prm1[512];
__device__ float g_prm2[512];
__device__ float g_pool[BB * HC];

// ---------------- zero scratch ----------------
__global__ void k_zero() {
    int stride = gridDim.x * blockDim.x;
    int i = blockIdx.x * blockDim.x + threadIdx.x;
    for (int j = i; j < NN; j += stride) g_deg[j] = 0;
    for (int j = i; j < BB; j += stride) g_counts[j] = 0;
    for (int j = i; j < 512; j += stride) { g_bn1[j] = 0.f; g_bn2[j] = 0.f; }
    for (int j = i; j < BB * HC; j += stride) g_pool[j] = 0.f;
}

// ---------------- graph counts ----------------
__global__ void k_counts(const int* __restrict__ batch) {
    __shared__ int sm[BB];
    int t = threadIdx.x;
    if (t < BB) sm[t] = 0;
    __syncthreads();
    int i = blockIdx.x * blockDim.x + t;
    if (i < NN) atomicAdd(&sm[batch[i]], 1);
    __syncthreads();
    if (t < BB && sm[t]) atomicAdd(&g_counts[t], sm[t]);
}

__global__ void k_graph_meta() {
    if (threadIdx.x == 0 && blockIdx.x == 0) {
        int acc = 0;
        for (int b = 0; b < BB; b++) {
            int c = g_counts[b];
            g_starts[b] = acc;
            acc += c;
            g_gs[b] = (int)ceilf(sqrtf((float)c));
        }
    }
}

// ---------------- CSR build ----------------
__global__ void k_degree(const int* __restrict__ ei) {
    int e = blockIdx.x * blockDim.x + threadIdx.x;
    if (e >= ETOT) return;
    int d = (e < EE) ? ei[EE + e] : (e - EE);
    atomicAdd(&g_deg[d], 1);
}

__global__ void k_scan1() {
    __shared__ int sm[SCAN_B];
    int t = threadIdx.x;
    int i = blockIdx.x * SCAN_B + t;
    int v = (i < NN) ? g_deg[i] : 0;
    sm[t] = v;
    __syncthreads();
    #pragma unroll
    for (int off = 1; off < SCAN_B; off <<= 1) {
        int xv = (t >= off) ? sm[t - off] : 0;
        __syncthreads();
        sm[t] += xv;
        __syncthreads();
    }
    if (i < NN) g_off[i] = sm[t];
    if (t == SCAN_B - 1) g_bsum[blockIdx.x] = sm[t];
}

__global__ void k_scan2() {
    if (threadIdx.x == 0) {
        int run = 0;
        for (int b = 0; b < NBLK; b++) {
            int t = g_bsum[b];
            g_bsum[b] = run;
            run += t;
        }
        g_off[NN] = run;
    }
}

__global__ void k_scan3() {
    int i = blockIdx.x * blockDim.x + threadIdx.x;
    if (i >= NN) return;
    int e = g_off[i] - g_deg[i] + g_bsum[i / SCAN_B];
    g_off[i] = e;
    g_cur[i] = e;
}

__global__ void k_scatter(const int* __restrict__ ei) {
    int e = blockIdx.x * blockDim.x + threadIdx.x;
    if (e >= ETOT) return;
    int s, d;
    if (e < EE) { s = ei[e]; d = ei[EE + e]; }
    else { s = d = e - EE; }
    int p = atomicAdd(&g_cur[d], 1);
    g_csr[p] = s;
}

// ---------------- tensor-core GEMM (tf32) + fused attn coeffs, fp16 C ------------
// C[M,256] = A[M,K] @ B[K,256].  BN=64 == head width -> blockIdx.y == head.
template <int K, bool FUSE_PE>
__global__ void k_gemm_tc(const float* __restrict__ A, const float* __restrict__ Bw,
                          __half* __restrict__ C, int M,
                          const float* __restrict__ x, const int* __restrict__ batch,
                          const float* __restrict__ Wpos, const float* __restrict__ bpos,
                          const float* __restrict__ a_src, const float* __restrict__ a_dst) {
    const int BM = 128, BN = 64, BK = 32;
    const int LDA = BK + 4;   // 36
    const int LDB = BN + 4;   // 68
    __shared__ float sm[BM * LDB];
    float* As = sm;
    float* Bs = sm + BM * LDA;

    int tid = threadIdx.x;
    int warp = tid >> 5;
    int wm = warp & 3;
    int wn = warp >> 2;
    int row0 = blockIdx.x * BM;
    int col0 = blockIdx.y * BN;

    wmma::fragment<wmma::accumulator, 16, 16, 8, float> acc[2][2];
    #pragma unroll
    for (int i = 0; i < 2; i++)
        #pragma unroll
        for (int j = 0; j < 2; j++) wmma::fill_fragment(acc[i][j], 0.f);

    for (int k0 = 0; k0 < K; k0 += BK) {
        if (!FUSE_PE || k0 < F_IN) {
            int r = tid >> 1;
            int cbase = (tid & 1) * 16;
            int gr = row0 + r;
            const float* src = FUSE_PE ? (x + (size_t)gr * F_IN + k0 + cbase)
                                       : (A + (size_t)gr * K + k0 + cbase);
            #pragma unroll
            for (int v = 0; v < 4; v++) {
                float4 val = make_float4(0.f, 0.f, 0.f, 0.f);
                if (gr < M) val = *(const float4*)(src + v * 4);
                float* d = &As[r * LDA + cbase + v * 4];
                d[0] = wmma::__float_to_tf32(val.x);
                d[1] = wmma::__float_to_tf32(val.y);
                d[2] = wmma::__float_to_tf32(val.z);
                d[3] = wmma::__float_to_tf32(val.w);
            }
        } else {
            int r = tid >> 1;
            int half_ = tid & 1;
            int gr = row0 + r;
            if (half_ == 0) {
                float p0 = 0.f, p1 = 0.f;
                if (gr < M) {
                    int b = batch[gr];
                    int g = g_gs[b];
                    int i = gr - g_starts[b];
                    int rowI = i / g;
                    int colI = i - rowI * g;
                    float denom = (float)(g - 1 > 1 ? g - 1 : 1);
                    p0 = (float)rowI / denom;
                    p1 = (float)colI / denom;
                }
                #pragma unroll
                for (int jj = 0; jj < 16; jj++) {
                    float v = (gr < M) ? (p0 * Wpos[jj] + p1 * Wpos[POS + jj] + bpos[jj]) : 0.f;
                    As[r * LDA + jj] = wmma::__float_to_tf32(v);
                }
            } else {
                #pragma unroll
                for (int jj = 0; jj < 16; jj++) As[r * LDA + 16 + jj] = 0.f;
            }
        }
        {
            int idx = tid * 8;
            int kk = idx >> 6;
            int cc = idx & 63;
            #pragma unroll
            for (int v = 0; v < 2; v++) {
                float4 val = make_float4(0.f, 0.f, 0.f, 0.f);
                if (k0 + kk < K) val = *(const float4*)&Bw[(size_t)(k0 + kk) * HC + col0 + cc + v * 4];
                float* d = &Bs[kk * LDB + cc + v * 4];
                d[0] = wmma::__float_to_tf32(val.x);
                d[1] = wmma::__float_to_tf32(val.y);
                d[2] = wmma::__float_to_tf32(val.z);
                d[3] = wmma::__float_to_tf32(val.w);
            }
        }
        __syncthreads();
        #pragma unroll
        for (int ks = 0; ks < BK; ks += 8) {
            wmma::fragment<wmma::matrix_a, 16, 16, 8, wmma::precision::tf32, wmma::row_major> af[2];
            wmma::fragment<wmma::matrix_b, 16, 16, 8, wmma::precision::tf32, wmma::row_major> bf[2];
            #pragma unroll
            for (int i = 0; i < 2; i++)
                wmma::load_matrix_sync(af[i], &As[(wm * 32 + i * 16) * LDA + ks], LDA);
            #pragma unroll
            for (int j = 0; j < 2; j++)
                wmma::load_matrix_sync(bf[j], &Bs[ks * LDB + wn * 32 + j * 16], LDB);
            #pragma unroll
            for (int i = 0; i < 2; i++)
                #pragma unroll
                for (int j = 0; j < 2; j++)
                    wmma::mma_sync(acc[i][j], af[i], bf[j], acc[i][j]);
        }
        __syncthreads();
    }

    // ---- epilogue: stage C tile in smem, fp16 writeout, attn coefficients ----
    #pragma unroll
    for (int i = 0; i < 2; i++)
        #pragma unroll
        for (int j = 0; j < 2; j++)
            wmma::store_matrix_sync(&sm[(wm * 32 + i * 16) * LDB + wn * 32 + j * 16],
                                    acc[i][j], LDB, wmma::mem_row_major);
    __syncthreads();

    // fp16 copy to C (half traffic)
    for (int e = tid; e < BM * BN / 2; e += 256) {
        int r = e >> 5;             // 32 half2 per 64-col row
        int c = (e & 31) * 2;
        int gr = row0 + r;
        if (gr < M) {
            __half2 hv = __floats2half2_rn(sm[r * LDB + c], sm[r * LDB + c + 1]);
            *(__half2*)&C[(size_t)gr * HC + col0 + c] = hv;
        }
    }

    // attn coefficients for this head (from fp32 smem tile)
    {
        int head = blockIdx.y;
        int r = tid >> 1;
        int halfc = (tid & 1) * 32;
        int gr = row0 + r;
        const float* av = a_src + head * 64;
        const float* dv = a_dst + head * 64;
        float ps = 0.f, pd = 0.f;
        #pragma unroll 8
        for (int k = 0; k < 32; k++) {
            float v = sm[r * LDB + halfc + k];
            ps += v * av[halfc + k];
            pd += v * dv[halfc + k];
        }
        ps += __shfl_xor_sync(0xFFFFFFFFu, ps, 1);
        pd += __shfl_xor_sync(0xFFFFFFFFu, pd, 1);
        if ((tid & 1) == 0 && gr < M) {
            g_as[gr * 4 + head] = ps;
            g_ad[gr * 4 + head] = pd;
        }
    }
}

// ---------------- softmax-aggregate (warp/node, fp16 h, no max pass) + BN stats ----
__global__ void k_agg(const __half* __restrict__ h, const float* __restrict__ bias,
                      float* __restrict__ out, float* __restrict__ bnsums) {
    int tid = threadIdx.x;
    int wp = tid >> 5;
    int lane = tid & 31;
    int node = blockIdx.x * 8 + wp;
    __shared__ float wsm[8][32][4];
    __shared__ float ssum[HC];
    __shared__ float ssum2[HC];
    ssum[tid] = 0.f;
    ssum2[tid] = 0.f;
    __syncthreads();

    int beg = g_off[node], end = g_off[node + 1];
    float ad0 = g_ad[node * 4 + 0], ad1 = g_ad[node * 4 + 1];
    float ad2 = g_ad[node * 4 + 2], ad3 = g_ad[node * 4 + 3];

    // single pass: w = exp(leaky_relu(as+ad))  (max-shift algebraically cancels)
    float2 acc0 = {0.f, 0.f}, acc1 = {0.f, 0.f}, acc2 = {0.f, 0.f}, acc3 = {0.f, 0.f};
    float sw0 = 0.f, sw1 = 0.f, sw2 = 0.f, sw3 = 0.f;
    for (int base = beg; base < end; base += 32) {
        int j = base + lane;
        float w0 = 0.f, w1 = 0.f, w2 = 0.f, w3 = 0.f;
        if (j < end) {
            int s = g_csr[j];
            const float* as = &g_as[s * 4];
            float v0 = as[0] + ad0; v0 = v0 > 0.f ? v0 : 0.2f * v0; w0 = __expf(v0);
            float v1 = as[1] + ad1; v1 = v1 > 0.f ? v1 : 0.2f * v1; w1 = __expf(v1);
            float v2 = as[2] + ad2; v2 = v2 > 0.f ? v2 : 0.2f * v2; w2 = __expf(v2);
            float v3 = as[3] + ad3; v3 = v3 > 0.f ? v3 : 0.2f * v3; w3 = __expf(v3);
        }
        wsm[wp][lane][0] = w0; wsm[wp][lane][1] = w1;
        wsm[wp][lane][2] = w2; wsm[wp][lane][3] = w3;
        sw0 += w0; sw1 += w1; sw2 += w2; sw3 += w3;
        __syncwarp();
        int cnt = end - base; if (cnt > 32) cnt = 32;
        for (int t = 0; t < cnt; t++) {
            int ss = g_csr[base + t];
            float wv0 = wsm[wp][t][0], wv1 = wsm[wp][t][1];
            float wv2 = wsm[wp][t][2], wv3 = wsm[wp][t][3];
            const __half2* hp = (const __half2*)(h + (size_t)ss * HC) + lane;
            float2 f0 = __half22float2(hp[0]);    // channels 2l,2l+1     (head 0)
            float2 f1 = __half22float2(hp[32]);   // +64                  (head 1)
            float2 f2 = __half22float2(hp[64]);   // +128                 (head 2)
            float2 f3 = __half22float2(hp[96]);   // +192                 (head 3)
            acc0.x += wv0 * f0.x; acc0.y += wv0 * f0.y;
            acc1.x += wv1 * f1.x; acc1.y += wv1 * f1.y;
            acc2.x += wv2 * f2.x; acc2.y += wv2 * f2.y;
            acc3.x += wv3 * f3.x; acc3.y += wv3 * f3.y;
        }
        __syncwarp();
    }
    #pragma unroll
    for (int off = 16; off; off >>= 1) {
        sw0 += __shfl_xor_sync(0xFFFFFFFFu, sw0, off);
        sw1 += __shfl_xor_sync(0xFFFFFFFFu, sw1, off);
        sw2 += __shfl_xor_sync(0xFFFFFFFFu, sw2, off);
        sw3 += __shfl_xor_sync(0xFFFFFFFFu, sw3, off);
    }
    float i0 = 1.f / sw0, i1 = 1.f / sw1, i2 = 1.f / sw2, i3 = 1.f / sw3;
    int c0 = 2 * lane;
    float2 r0, r1, r2, r3;
    r0.x = acc0.x * i0 + bias[c0];        r0.y = acc0.y * i0 + bias[c0 + 1];
    r1.x = acc1.x * i1 + bias[c0 + 64];   r1.y = acc1.y * i1 + bias[c0 + 65];
    r2.x = acc2.x * i2 + bias[c0 + 128];  r2.y = acc2.y * i2 + bias[c0 + 129];
    r3.x = acc3.x * i3 + bias[c0 + 192];  r3.y = acc3.y * i3 + bias[c0 + 193];
    float* op = &out[(size_t)node * HC];
    *(float2*)&op[c0]       = r0;
    *(float2*)&op[c0 + 64]  = r1;
    *(float2*)&op[c0 + 128] = r2;
    *(float2*)&op[c0 + 192] = r3;
    atomicAdd(&ssum[c0], r0.x);        atomicAdd(&ssum[c0 + 1], r0.y);
    atomicAdd(&ssum[c0 + 64], r1.x);   atomicAdd(&ssum[c0 + 65], r1.y);
    atomicAdd(&ssum[c0 + 128], r2.x);  atomicAdd(&ssum[c0 + 129], r2.y);
    atomicAdd(&ssum[c0 + 192], r3.x);  atomicAdd(&ssum[c0 + 193], r3.y);
    atomicAdd(&ssum2[c0], r0.x * r0.x);        atomicAdd(&ssum2[c0 + 1], r0.y * r0.y);
    atomicAdd(&ssum2[c0 + 64], r1.x * r1.x);   atomicAdd(&ssum2[c0 + 65], r1.y * r1.y);
    atomicAdd(&ssum2[c0 + 128], r2.x * r2.x);  atomicAdd(&ssum2[c0 + 129], r2.y * r2.y);
    atomicAdd(&ssum2[c0 + 192], r3.x * r3.x);  atomicAdd(&ssum2[c0 + 193], r3.y * r3.y);
    __syncthreads();
    atomicAdd(&bnsums[tid], ssum[tid]);
    atomicAdd(&bnsums[HC + tid], ssum2[tid]);
}

// ---------------- batch norm finalize ----------------
__global__ void k_bn_fin(const float* __restrict__ sums, const float* __restrict__ gamma,
                         const float* __restrict__ beta, float* __restrict__ prm) {
    int ch = threadIdx.x;
    float mean = sums[ch] / (float)NN;
    float var = sums[HC + ch] / (float)NN - mean * mean;
    float inv = rsqrtf(var + 1e-5f);
    float sc = gamma[ch] * inv;
    prm[ch] = sc;
    prm[HC + ch] = beta[ch] - mean * sc;
}

// BN+ELU in place (layer 1 output feeds GEMM2), float4-vectorized
__global__ void k_bn_elu(float* __restrict__ x, const float* __restrict__ prm) {
    long i4 = (long)blockIdx.x * blockDim.x + threadIdx.x;
    if (i4 >= (long)NN * HC / 4) return;
    int ch = (int)(i4 & (HC / 4 - 1)) * 4;
    float4 v = *(float4*)&x[i4 * 4];
    float4 s = *(const float4*)&prm[ch];
    float4 o = *(const float4*)&prm[HC + ch];
    v.x = v.x * s.x + o.x; v.x = v.x > 0.f ? v.x : (__expf(v.x) - 1.f);
    v.y = v.y * s.y + o.y; v.y = v.y > 0.f ? v.y : (__expf(v.y) - 1.f);
    v.z = v.z * s.z + o.z; v.z = v.z > 0.f ? v.z : (__expf(v.z) - 1.f);
    v.w = v.w * s.w + o.w; v.w = v.w > 0.f ? v.w : (__expf(v.w) - 1.f);
    *(float4*)&x[i4 * 4] = v;
}

// layer 2: BN+ELU fused directly into pooling (no activation writeback)
__global__ void k_bn_elu_pool(const float* __restrict__ x, const float* __restrict__ prm,
                              const int* __restrict__ batch) {
    int ch = threadIdx.x;
    int r0 = blockIdx.x * 128;
    int rend = r0 + 128; if (rend > NN) rend = NN;
    float sc = prm[ch], of = prm[HC + ch];
    float acc = 0.f;
    int gcur = batch[r0];
    for (int r = r0; r < rend; r++) {
        int g = batch[r];
        if (g != gcur) {
            atomicAdd(&g_pool[gcur * HC + ch], acc);
            acc = 0.f;
            gcur = g;
        }
        float v = x[(size_t)r * HC + ch] * sc + of;
        acc += (v > 0.f ? v : (__expf(v) - 1.f));
    }
    atomicAdd(&g_pool[gcur * HC + ch], acc);
}

__global__ void k_fc(const float* __restrict__ Wfc, const float* __restrict__ bfc,
                     float* __restrict__ out) {
    int g = blockIdx.x, o = threadIdx.x;
    __shared__ float ps[HC];
    float invc = 1.f / (float)g_counts[g];
    for (int c = o; c < HC; c += OUT_DIM) ps[c] = g_pool[g * HC + c] * invc;
    __syncthreads();
    float acc = bfc[o];
    #pragma unroll 8
    for (int c = 0; c < HC; c++) acc += ps[c] * Wfc[c * OUT_DIM + o];
    out[g * OUT_DIM + o] = acc;
}

// ---------------- launch ----------------
extern "C" void kernel_launch(void* const* d_in, const int* in_sizes, int n_in,
                              void* d_out, int out_size) {
    const float* x       = (const float*)d_in[0];
    const int*   ei      = (const int*)d_in[1];
    const int*   batch   = (const int*)d_in[2];
    const float* W_pos   = (const float*)d_in[3];
    const float* b_pos   = (const float*)d_in[4];
    const float* W1      = (const float*)d_in[5];
    const float* a_src1  = (const float*)d_in[6];
    const float* a_dst1  = (const float*)d_in[7];
    const float* b1      = (const float*)d_in[8];
    const float* gamma1  = (const float*)d_in[9];
    const float* beta1   = (const float*)d_in[10];
    const float* W2      = (const float*)d_in[11];
    const float* a_src2  = (const float*)d_in[12];
    const float* a_dst2  = (const float*)d_in[13];
    const float* b2      = (const float*)d_in[14];
    const float* gamma2  = (const float*)d_in[15];
    const float* beta2   = (const float*)d_in[16];
    const float* W_fc    = (const float*)d_in[17];
    const float* b_fc    = (const float*)d_in[18];
    float* out = (float*)d_out;

    __half* hH;
    float *hF, *bn1, *bn2, *prm1, *prm2;
    cudaGetSymbolAddress((void**)&hH, g_hH);
    cudaGetSymbolAddress((void**)&hF, g_hF);
    cudaGetSymbolAddress((void**)&bn1, g_bn1);
    cudaGetSymbolAddress((void**)&bn2, g_bn2);
    cudaGetSymbolAddress((void**)&prm1, g_prm1);
    cudaGetSymbolAddress((void**)&prm2, g_prm2);

    // setup
    k_zero<<<256, 256>>>();
    k_counts<<<(NN + 255) / 256, 256>>>(batch);
    k_graph_meta<<<1, 32>>>();
    k_degree<<<(ETOT + 255) / 256, 256>>>(ei);
    k_scan1<<<NBLK, SCAN_B>>>();
    k_scan2<<<1, 32>>>();
    k_scan3<<<(NN + 255) / 256, 256>>>();
    k_scatter<<<(ETOT + 255) / 256, 256>>>(ei);

    dim3 gg((NN + 127) / 128, HC / 64);

    // layer 1 (PE + attn coefficients fused into GEMM; fp16 h out)
    k_gemm_tc<ENH, true><<<gg, 256>>>(nullptr, W1, hH, NN, x, batch, W_pos, b_pos,
                                      a_src1, a_dst1);
    k_agg<<<NN / 8, 256>>>(hH, b1, hF, bn1);
    k_bn_fin<<<1, 256>>>(bn1, gamma1, beta1, prm1);
    k_bn_elu<<<(int)(((long)NN * HC / 4 + 255) / 256), 256>>>(hF, prm1);

    // layer 2
    k_gemm_tc<HC, false><<<gg, 256>>>(hF, W2, hH, NN, nullptr, nullptr, nullptr, nullptr,
                                      a_src2, a_dst2);
    k_agg<<<NN / 8, 256>>>(hH, b2, hF, bn2);
    k_bn_fin<<<1, 256>>>(bn2, gamma2, beta2, prm2);

    // fused BN+ELU+pool
    k_bn_elu_pool<<<(NN + 127) / 128, 256>>>(hF, prm2, batch);
    k_fc<<<BB, OUT_DIM>>>(W_fc, b_fc, out);
}

// round 8
// speedup vs baseline: 2.0092x; 1.2672x over previous
#include <cuda_runtime.h>
#include <cuda_fp16.h>
#include <math.h>
#include <mma.h>

using namespace nvcuda;

#define NN 50000
#define EE 800000
#define ETOT (EE + NN)
#define BB 64
#define F_IN 128
#define POS 16
#define ENH 144
#define HC 256
#define OUT_DIM 128
#define SCAN_B 1024
#define NBLK ((NN + SCAN_B - 1) / SCAN_B)   // 49

// ---------------- scratch (device globals; no allocation allowed) ----------------
__device__ __half g_hH[(size_t)NN * HC];    // GEMM output (feeds aggregation only)
__device__ __half g_xH[(size_t)NN * HC];    // BN+ELU output (feeds GEMM2 A)
__device__ float  g_hF[(size_t)NN * HC];    // agg output / BN stats source
__device__ float g_as[NN * 4];
__device__ float g_ad[NN * 4];
__device__ int   g_deg[NN];
__device__ int   g_off[NN + 1];
__device__ int   g_cur[NN];
__device__ int   g_csr[ETOT];
__device__ int   g_bsum[NBLK];
__device__ int   g_counts[BB];
__device__ int   g_starts[BB];
__device__ int   g_gs[BB];
__device__ float g_bn1[512];
__device__ float g_bn2[512];
__device__ float g_prm1[512];
__device__ float g_prm2[512];
__device__ float g_pool[BB * HC];

// ---------------- zero scratch ----------------
__global__ void k_zero() {
    int stride = gridDim.x * blockDim.x;
    int i = blockIdx.x * blockDim.x + threadIdx.x;
    for (int j = i; j < NN; j += stride) g_deg[j] = 0;
    for (int j = i; j < BB; j += stride) g_counts[j] = 0;
    for (int j = i; j < 512; j += stride) { g_bn1[j] = 0.f; g_bn2[j] = 0.f; }
    for (int j = i; j < BB * HC; j += stride) g_pool[j] = 0.f;
}

// ---------------- graph counts ----------------
__global__ void k_counts(const int* __restrict__ batch) {
    __shared__ int sm[BB];
    int t = threadIdx.x;
    if (t < BB) sm[t] = 0;
    __syncthreads();
    int i = blockIdx.x * blockDim.x + t;
    if (i < NN) atomicAdd(&sm[batch[i]], 1);
    __syncthreads();
    if (t < BB && sm[t]) atomicAdd(&g_counts[t], sm[t]);
}

__global__ void k_graph_meta() {
    if (threadIdx.x == 0 && blockIdx.x == 0) {
        int acc = 0;
        for (int b = 0; b < BB; b++) {
            int c = g_counts[b];
            g_starts[b] = acc;
            acc += c;
            g_gs[b] = (int)ceilf(sqrtf((float)c));
        }
    }
}

// ---------------- CSR build ----------------
__global__ void k_degree(const int* __restrict__ ei) {
    int e = blockIdx.x * blockDim.x + threadIdx.x;
    if (e >= ETOT) return;
    int d = (e < EE) ? ei[EE + e] : (e - EE);
    atomicAdd(&g_deg[d], 1);
}

__global__ void k_scan1() {
    __shared__ int sm[SCAN_B];
    int t = threadIdx.x;
    int i = blockIdx.x * SCAN_B + t;
    int v = (i < NN) ? g_deg[i] : 0;
    sm[t] = v;
    __syncthreads();
    #pragma unroll
    for (int off = 1; off < SCAN_B; off <<= 1) {
        int xv = (t >= off) ? sm[t - off] : 0;
        __syncthreads();
        sm[t] += xv;
        __syncthreads();
    }
    if (i < NN) g_off[i] = sm[t];
    if (t == SCAN_B - 1) g_bsum[blockIdx.x] = sm[t];
}

__global__ void k_scan2() {
    if (threadIdx.x == 0) {
        int run = 0;
        for (int b = 0; b < NBLK; b++) {
            int t = g_bsum[b];
            g_bsum[b] = run;
            run += t;
        }
        g_off[NN] = run;
    }
}

__global__ void k_scan3() {
    int i = blockIdx.x * blockDim.x + threadIdx.x;
    if (i >= NN) return;
    int e = g_off[i] - g_deg[i] + g_bsum[i / SCAN_B];
    g_off[i] = e;
    g_cur[i] = e;
}

__global__ void k_scatter(const int* __restrict__ ei) {
    int e = blockIdx.x * blockDim.x + threadIdx.x;
    if (e >= ETOT) return;
    int s, d;
    if (e < EE) { s = ei[e]; d = ei[EE + e]; }
    else { s = d = e - EE; }
    int p = atomicAdd(&g_cur[d], 1);
    g_csr[p] = s;
}

// ---------------- tensor-core GEMM (fp16 in, fp32 acc) + fused attn coeffs --------
// C[M,256] = A[M,K] @ B[K,256].  BN=64 == head width -> blockIdx.y == head.
template <int K, bool FUSE_PE, bool A_HALF>
__global__ void k_gemm_tc(const float* __restrict__ Af, const __half* __restrict__ Ah,
                          const float* __restrict__ Bw,
                          __half* __restrict__ C, int M,
                          const float* __restrict__ x, const int* __restrict__ batch,
                          const float* __restrict__ Wpos, const float* __restrict__ bpos,
                          const float* __restrict__ a_src, const float* __restrict__ a_dst) {
    const int BM = 128, BN = 64, BK = 32;
    const int LDAH = 40;     // half elements per A row (32 + 8 pad)
    const int LDBH = 72;     // half elements per B row (64 + 8 pad)
    const int LDB = BN + 4;  // float epilogue staging stride (68)
    __shared__ float sm[BM * LDB];                 // 34816 B
    __half* As = (__half*)sm;                      // 128*40*2 = 10240 B
    __half* Bs = ((__half*)sm) + BM * LDAH;        // 32*72*2  =  4608 B

    int tid = threadIdx.x;
    int warp = tid >> 5;
    int wm = warp & 3;
    int wn = warp >> 2;
    int row0 = blockIdx.x * BM;
    int col0 = blockIdx.y * BN;

    wmma::fragment<wmma::accumulator, 16, 16, 16, float> acc[2][2];
    #pragma unroll
    for (int i = 0; i < 2; i++)
        #pragma unroll
        for (int j = 0; j < 2; j++) wmma::fill_fragment(acc[i][j], 0.f);

    for (int k0 = 0; k0 < K; k0 += BK) {
        // ---- A tile: 128 rows x 32 k (half) ----
        {
            int r = tid >> 1;
            int cbase = (tid & 1) * 16;
            int gr = row0 + r;
            __half* dst = &As[r * LDAH + cbase];
            if (FUSE_PE && k0 >= F_IN) {
                if (cbase == 0) {
                    float p0 = 0.f, p1 = 0.f;
                    if (gr < M) {
                        int b = batch[gr];
                        int g = g_gs[b];
                        int i = gr - g_starts[b];
                        int rowI = i / g;
                        int colI = i - rowI * g;
                        float denom = (float)(g - 1 > 1 ? g - 1 : 1);
                        p0 = (float)rowI / denom;
                        p1 = (float)colI / denom;
                    }
                    #pragma unroll
                    for (int jj = 0; jj < 16; jj += 2) {
                        float v0 = (gr < M) ? (p0 * Wpos[jj] + p1 * Wpos[POS + jj] + bpos[jj]) : 0.f;
                        float v1 = (gr < M) ? (p0 * Wpos[jj + 1] + p1 * Wpos[POS + jj + 1] + bpos[jj + 1]) : 0.f;
                        *(__half2*)&dst[jj] = __floats2half2_rn(v0, v1);
                    }
                } else {
                    #pragma unroll
                    for (int jj = 0; jj < 16; jj += 2)
                        *(__half2*)&dst[jj] = __floats2half2_rn(0.f, 0.f);
                }
            } else if (A_HALF) {
                const float4* src = (const float4*)(Ah + (size_t)gr * K + k0 + cbase);
                float4 v0 = make_float4(0.f, 0.f, 0.f, 0.f), v1 = v0;
                if (gr < M) { v0 = src[0]; v1 = src[1]; }
                *(float4*)&dst[0] = v0;
                *(float4*)&dst[8] = v1;
            } else {
                const float* src = FUSE_PE ? (x + (size_t)gr * F_IN + k0 + cbase)
                                           : (Af + (size_t)gr * K + k0 + cbase);
                #pragma unroll
                for (int v = 0; v < 4; v++) {
                    float4 val = make_float4(0.f, 0.f, 0.f, 0.f);
                    if (gr < M) val = *(const float4*)(src + v * 4);
                    *(__half2*)&dst[v * 4]     = __floats2half2_rn(val.x, val.y);
                    *(__half2*)&dst[v * 4 + 2] = __floats2half2_rn(val.z, val.w);
                }
            }
        }
        // ---- B tile: 32 k x 64 cols (half) ----
        {
            int idx = tid * 8;
            int kk = idx >> 6;
            int cc = idx & 63;
            const float* src = &Bw[(size_t)(k0 + kk) * HC + col0 + cc];
            float4 v0 = *(const float4*)src;
            float4 v1 = *(const float4*)(src + 4);
            __half* d = &Bs[kk * LDBH + cc];
            *(__half2*)&d[0] = __floats2half2_rn(v0.x, v0.y);
            *(__half2*)&d[2] = __floats2half2_rn(v0.z, v0.w);
            *(__half2*)&d[4] = __floats2half2_rn(v1.x, v1.y);
            *(__half2*)&d[6] = __floats2half2_rn(v1.z, v1.w);
        }
        __syncthreads();
        #pragma unroll
        for (int ks = 0; ks < BK; ks += 16) {
            wmma::fragment<wmma::matrix_a, 16, 16, 16, __half, wmma::row_major> af[2];
            wmma::fragment<wmma::matrix_b, 16, 16, 16, __half, wmma::row_major> bf[2];
            #pragma unroll
            for (int i = 0; i < 2; i++)
                wmma::load_matrix_sync(af[i], &As[(wm * 32 + i * 16) * LDAH + ks], LDAH);
            #pragma unroll
            for (int j = 0; j < 2; j++)
                wmma::load_matrix_sync(bf[j], &Bs[ks * LDBH + wn * 32 + j * 16], LDBH);
            #pragma unroll
            for (int i = 0; i < 2; i++)
                #pragma unroll
                for (int j = 0; j < 2; j++)
                    wmma::mma_sync(acc[i][j], af[i], bf[j], acc[i][j]);
        }
        __syncthreads();
    }

    // ---- epilogue: stage C tile in fp32 smem, fp16 writeout, attn coefficients ----
    #pragma unroll
    for (int i = 0; i < 2; i++)
        #pragma unroll
        for (int j = 0; j < 2; j++)
            wmma::store_matrix_sync(&sm[(wm * 32 + i * 16) * LDB + wn * 32 + j * 16],
                                    acc[i][j], LDB, wmma::mem_row_major);
    __syncthreads();

    for (int e = tid; e < BM * BN / 2; e += 256) {
        int r = e >> 5;
        int c = (e & 31) * 2;
        int gr = row0 + r;
        if (gr < M) {
            __half2 hv = __floats2half2_rn(sm[r * LDB + c], sm[r * LDB + c + 1]);
            *(__half2*)&C[(size_t)gr * HC + col0 + c] = hv;
        }
    }

    {
        int head = blockIdx.y;
        int r = tid >> 1;
        int halfc = (tid & 1) * 32;
        int gr = row0 + r;
        const float* av = a_src + head * 64;
        const float* dv = a_dst + head * 64;
        float ps = 0.f, pd = 0.f;
        #pragma unroll 8
        for (int k = 0; k < 32; k++) {
            float v = sm[r * LDB + halfc + k];
            ps += v * av[halfc + k];
            pd += v * dv[halfc + k];
        }
        ps += __shfl_xor_sync(0xFFFFFFFFu, ps, 1);
        pd += __shfl_xor_sync(0xFFFFFFFFu, pd, 1);
        if ((tid & 1) == 0 && gr < M) {
            g_as[gr * 4 + head] = ps;
            g_ad[gr * 4 + head] = pd;
        }
    }
}

// ---------------- softmax-aggregate (warp/node, fp16 h, unrolled MLP) + BN stats --
__global__ void k_agg(const __half* __restrict__ h, const float* __restrict__ bias,
                      float* __restrict__ out, float* __restrict__ bnsums) {
    int tid = threadIdx.x;
    int wp = tid >> 5;
    int lane = tid & 31;
    int node = blockIdx.x * 8 + wp;
    __shared__ float wsm[8][32][4];
    __shared__ int   ssm[8][32];
    __shared__ float ssum[HC];
    __shared__ float ssum2[HC];
    ssum[tid] = 0.f;
    ssum2[tid] = 0.f;
    __syncthreads();

    int beg = g_off[node], end = g_off[node + 1];
    float ad0 = g_ad[node * 4 + 0], ad1 = g_ad[node * 4 + 1];
    float ad2 = g_ad[node * 4 + 2], ad3 = g_ad[node * 4 + 3];

    float2 acc0 = {0.f, 0.f}, acc1 = {0.f, 0.f}, acc2 = {0.f, 0.f}, acc3 = {0.f, 0.f};
    float sw0 = 0.f, sw1 = 0.f, sw2 = 0.f, sw3 = 0.f;
    for (int base = beg; base < end; base += 32) {
        int j = base + lane;
        float w0 = 0.f, w1 = 0.f, w2 = 0.f, w3 = 0.f;
        int s = beg < end ? g_csr[(j < end) ? j : beg] : 0;  // clamped valid index
        if (j < end) {
            const float* as = &g_as[s * 4];
            float v0 = as[0] + ad0; v0 = v0 > 0.f ? v0 : 0.2f * v0; w0 = __expf(v0);
            float v1 = as[1] + ad1; v1 = v1 > 0.f ? v1 : 0.2f * v1; w1 = __expf(v1);
            float v2 = as[2] + ad2; v2 = v2 > 0.f ? v2 : 0.2f * v2; w2 = __expf(v2);
            float v3 = as[3] + ad3; v3 = v3 > 0.f ? v3 : 0.2f * v3; w3 = __expf(v3);
        }
        wsm[wp][lane][0] = w0; wsm[wp][lane][1] = w1;
        wsm[wp][lane][2] = w2; wsm[wp][lane][3] = w3;
        ssm[wp][lane] = s;
        sw0 += w0; sw1 += w1; sw2 += w2; sw3 += w3;
        __syncwarp();
        int cnt = end - base; if (cnt > 32) cnt = 32;
        int cnt4 = (cnt + 3) & ~3;   // OOR edges have w=0, clamped valid src
        for (int t = 0; t < cnt4; t += 4) {
            float2 f[4][4];
            float wv[4][4];
            #pragma unroll
            for (int u = 0; u < 4; u++) {
                int ss = ssm[wp][t + u];
                const __half2* hp = (const __half2*)(h + (size_t)ss * HC) + lane;
                f[u][0] = __half22float2(hp[0]);
                f[u][1] = __half22float2(hp[32]);
                f[u][2] = __half22float2(hp[64]);
                f[u][3] = __half22float2(hp[96]);
                wv[u][0] = wsm[wp][t + u][0];
                wv[u][1] = wsm[wp][t + u][1];
                wv[u][2] = wsm[wp][t + u][2];
                wv[u][3] = wsm[wp][t + u][3];
            }
            #pragma unroll
            for (int u = 0; u < 4; u++) {
                acc0.x += wv[u][0] * f[u][0].x; acc0.y += wv[u][0] * f[u][0].y;
                acc1.x += wv[u][1] * f[u][1].x; acc1.y += wv[u][1] * f[u][1].y;
                acc2.x += wv[u][2] * f[u][2].x; acc2.y += wv[u][2] * f[u][2].y;
                acc3.x += wv[u][3] * f[u][3].x; acc3.y += wv[u][3] * f[u][3].y;
            }
        }
        __syncwarp();
    }
    #pragma unroll
    for (int off = 16; off; off >>= 1) {
        sw0 += __shfl_xor_sync(0xFFFFFFFFu, sw0, off);
        sw1 += __shfl_xor_sync(0xFFFFFFFFu, sw1, off);
        sw2 += __shfl_xor_sync(0xFFFFFFFFu, sw2, off);
        sw3 += __shfl_xor_sync(0xFFFFFFFFu, sw3, off);
    }
    float i0 = 1.f / sw0, i1 = 1.f / sw1, i2 = 1.f / sw2, i3 = 1.f / sw3;
    int c0 = 2 * lane;
    float2 r0, r1, r2, r3;
    r0.x = acc0.x * i0 + bias[c0];        r0.y = acc0.y * i0 + bias[c0 + 1];
    r1.x = acc1.x * i1 + bias[c0 + 64];   r1.y = acc1.y * i1 + bias[c0 + 65];
    r2.x = acc2.x * i2 + bias[c0 + 128];  r2.y = acc2.y * i2 + bias[c0 + 129];
    r3.x = acc3.x * i3 + bias[c0 + 192];  r3.y = acc3.y * i3 + bias[c0 + 193];
    float* op = &out[(size_t)node * HC];
    *(float2*)&op[c0]       = r0;
    *(float2*)&op[c0 + 64]  = r1;
    *(float2*)&op[c0 + 128] = r2;
    *(float2*)&op[c0 + 192] = r3;
    atomicAdd(&ssum[c0], r0.x);        atomicAdd(&ssum[c0 + 1], r0.y);
    atomicAdd(&ssum[c0 + 64], r1.x);   atomicAdd(&ssum[c0 + 65], r1.y);
    atomicAdd(&ssum[c0 + 128], r2.x);  atomicAdd(&ssum[c0 + 129], r2.y);
    atomicAdd(&ssum[c0 + 192], r3.x);  atomicAdd(&ssum[c0 + 193], r3.y);
    atomicAdd(&ssum2[c0], r0.x * r0.x);        atomicAdd(&ssum2[c0 + 1], r0.y * r0.y);
    atomicAdd(&ssum2[c0 + 64], r1.x * r1.x);   atomicAdd(&ssum2[c0 + 65], r1.y * r1.y);
    atomicAdd(&ssum2[c0 + 128], r2.x * r2.x);  atomicAdd(&ssum2[c0 + 129], r2.y * r2.y);
    atomicAdd(&ssum2[c0 + 192], r3.x * r3.x);  atomicAdd(&ssum2[c0 + 193], r3.y * r3.y);
    __syncthreads();
    atomicAdd(&bnsums[tid], ssum[tid]);
    atomicAdd(&bnsums[HC + tid], ssum2[tid]);
}

// ---------------- batch norm finalize ----------------
__global__ void k_bn_fin(const float* __restrict__ sums, const float* __restrict__ gamma,
                         const float* __restrict__ beta, float* __restrict__ prm) {
    int ch = threadIdx.x;
    float mean = sums[ch] / (float)NN;
    float var = sums[HC + ch] / (float)NN - mean * mean;
    float inv = rsqrtf(var + 1e-5f);
    float sc = gamma[ch] * inv;
    prm[ch] = sc;
    prm[HC + ch] = beta[ch] - mean * sc;
}

// BN+ELU: fp32 in -> fp16 out (feeds GEMM2 A only)
__global__ void k_bn_elu(const float* __restrict__ x, const float* __restrict__ prm,
                         __half* __restrict__ xo) {
    long i4 = (long)blockIdx.x * blockDim.x + threadIdx.x;
    if (i4 >= (long)NN * HC / 4) return;
    int ch = (int)(i4 & (HC / 4 - 1)) * 4;
    float4 v = *(const float4*)&x[i4 * 4];
    float4 s = *(const float4*)&prm[ch];
    float4 o = *(const float4*)&prm[HC + ch];
    v.x = v.x * s.x + o.x; v.x = v.x > 0.f ? v.x : (__expf(v.x) - 1.f);
    v.y = v.y * s.y + o.y; v.y = v.y > 0.f ? v.y : (__expf(v.y) - 1.f);
    v.z = v.z * s.z + o.z; v.z = v.z > 0.f ? v.z : (__expf(v.z) - 1.f);
    v.w = v.w * s.w + o.w; v.w = v.w > 0.f ? v.w : (__expf(v.w) - 1.f);
    __half2 h0 = __floats2half2_rn(v.x, v.y);
    __half2 h1 = __floats2half2_rn(v.z, v.w);
    *(__half2*)&xo[i4 * 4]     = h0;
    *(__half2*)&xo[i4 * 4 + 2] = h1;
}

// layer 2: BN+ELU fused directly into pooling (no activation writeback)
__global__ void k_bn_elu_pool(const float* __restrict__ x, const float* __restrict__ prm,
                              const int* __restrict__ batch) {
    int ch = threadIdx.x;
    int r0 = blockIdx.x * 128;
    int rend = r0 + 128; if (rend > NN) rend = NN;
    float sc = prm[ch], of = prm[HC + ch];
    float acc = 0.f;
    int gcur = batch[r0];
    for (int r = r0; r < rend; r++) {
        int g = batch[r];
        if (g != gcur) {
            atomicAdd(&g_pool[gcur * HC + ch], acc);
            acc = 0.f;
            gcur = g;
        }
        float v = x[(size_t)r * HC + ch] * sc + of;
        acc += (v > 0.f ? v : (__expf(v) - 1.f));
    }
    atomicAdd(&g_pool[gcur * HC + ch], acc);
}

__global__ void k_fc(const float* __restrict__ Wfc, const float* __restrict__ bfc,
                     float* __restrict__ out) {
    int g = blockIdx.x, o = threadIdx.x;
    __shared__ float ps[HC];
    float invc = 1.f / (float)g_counts[g];
    for (int c = o; c < HC; c += OUT_DIM) ps[c] = g_pool[g * HC + c] * invc;
    __syncthreads();
    float acc = bfc[o];
    #pragma unroll 8
    for (int c = 0; c < HC; c++) acc += ps[c] * Wfc[c * OUT_DIM + o];
    out[g * OUT_DIM + o] = acc;
}

// ---------------- launch ----------------
extern "C" void kernel_launch(void* const* d_in, const int* in_sizes, int n_in,
                              void* d_out, int out_size) {
    const float* x       = (const float*)d_in[0];
    const int*   ei      = (const int*)d_in[1];
    const int*   batch   = (const int*)d_in[2];
    const float* W_pos   = (const float*)d_in[3];
    const float* b_pos   = (const float*)d_in[4];
    const float* W1      = (const float*)d_in[5];
    const float* a_src1  = (const float*)d_in[6];
    const float* a_dst1  = (const float*)d_in[7];
    const float* b1      = (const float*)d_in[8];
    const float* gamma1  = (const float*)d_in[9];
    const float* beta1   = (const float*)d_in[10];
    const float* W2      = (const float*)d_in[11];
    const float* a_src2  = (const float*)d_in[12];
    const float* a_dst2  = (const float*)d_in[13];
    const float* b2      = (const float*)d_in[14];
    const float* gamma2  = (const float*)d_in[15];
    const float* beta2   = (const float*)d_in[16];
    const float* W_fc    = (const float*)d_in[17];
    const float* b_fc    = (const float*)d_in[18];
    float* out = (float*)d_out;

    __half *hH, *xH;
    float *hF, *bn1, *bn2, *prm1, *prm2;
    cudaGetSymbolAddress((void**)&hH, g_hH);
    cudaGetSymbolAddress((void**)&xH, g_xH);
    cudaGetSymbolAddress((void**)&hF, g_hF);
    cudaGetSymbolAddress((void**)&bn1, g_bn1);
    cudaGetSymbolAddress((void**)&bn2, g_bn2);
    cudaGetSymbolAddress((void**)&prm1, g_prm1);
    cudaGetSymbolAddress((void**)&prm2, g_prm2);

    // setup
    k_zero<<<256, 256>>>();
    k_counts<<<(NN + 255) / 256, 256>>>(batch);
    k_graph_meta<<<1, 32>>>();
    k_degree<<<(ETOT + 255) / 256, 256>>>(ei);
    k_scan1<<<NBLK, SCAN_B>>>();
    k_scan2<<<1, 32>>>();
    k_scan3<<<(NN + 255) / 256, 256>>>();
    k_scatter<<<(ETOT + 255) / 256, 256>>>(ei);

    dim3 gg((NN + 127) / 128, HC / 64);

    // layer 1 (PE + attn coefficients fused into GEMM; fp16 h out)
    k_gemm_tc<ENH, true, false><<<gg, 256>>>(nullptr, nullptr, W1, hH, NN,
                                             x, batch, W_pos, b_pos, a_src1, a_dst1);
    k_agg<<<NN / 8, 256>>>(hH, b1, hF, bn1);
    k_bn_fin<<<1, 256>>>(bn1, gamma1, beta1, prm1);
    k_bn_elu<<<(int)(((long)NN * HC / 4 + 255) / 256), 256>>>(hF, prm1, xH);

    // layer 2 (fp16 A operand)
    k_gemm_tc<HC, false, true><<<gg, 256>>>(nullptr, xH, W2, hH, NN,
                                            nullptr, nullptr, nullptr, nullptr, a_src2, a_dst2);
    k_agg<<<NN / 8, 256>>>(hH, b2, hF, bn2);
    k_bn_fin<<<1, 256>>>(bn2, gamma2, beta2, prm2);

    // fused BN+ELU+pool
    k_bn_elu_pool<<<(NN + 127) / 128, 256>>>(hF, prm2, batch);
    k_fc<<<BB, OUT_DIM>>>(W_fc, b_fc, out);
}

// round 9
// speedup vs baseline: 2.1680x; 1.0791x over previous
#include <cuda_runtime.h>
#include <cuda_fp16.h>
#include <math.h>
#include <mma.h>

using namespace nvcuda;

#define NN 50000
#define EE 800000
#define ETOT (EE + NN)
#define BB 64
#define F_IN 128
#define POS 16
#define ENH 144
#define HC 256
#define OUT_DIM 128
#define SCAN_B 1024
#define NBLK ((NN + SCAN_B - 1) / SCAN_B)   // 49

// ---------------- scratch (device globals; no allocation allowed) ----------------
__device__ __half g_hH[(size_t)NN * HC];    // GEMM output (feeds aggregation only)
__device__ __half g_xH[(size_t)NN * HC];    // BN+ELU output (feeds GEMM2 A)
__device__ float  g_hF[(size_t)NN * HC];    // agg output / BN stats source
__device__ float g_as[NN * 4];
__device__ float g_ad[NN * 4];
__device__ int   g_deg[NN];
__device__ int   g_off[NN + 1];
__device__ int   g_cur[NN];
__device__ int   g_csr[ETOT];
__device__ int   g_bsum[NBLK];
__device__ int   g_counts[BB];
__device__ int   g_starts[BB];
__device__ int   g_gs[BB];
__device__ float g_bn1[512];
__device__ float g_bn2[512];
__device__ float g_prm1[512];
__device__ float g_prm2[512];
__device__ float g_pool[BB * HC];

// ---------------- side stream + events (host-side resources, created once) -------
static cudaStream_t g_s2 = nullptr;
static cudaEvent_t  g_evFork = nullptr, g_evJoin = nullptr;
static struct StreamInit {
    StreamInit() {
        cudaStreamCreateWithFlags(&g_s2, cudaStreamNonBlocking);
        cudaEventCreateWithFlags(&g_evFork, cudaEventDisableTiming);
        cudaEventCreateWithFlags(&g_evJoin, cudaEventDisableTiming);
    }
} g_streamInit;

// ---------------- zero scratch ----------------
__global__ void k_zero() {
    int stride = gridDim.x * blockDim.x;
    int i = blockIdx.x * blockDim.x + threadIdx.x;
    for (int j = i; j < NN; j += stride) g_deg[j] = 0;
    for (int j = i; j < BB; j += stride) g_counts[j] = 0;
    for (int j = i; j < 512; j += stride) { g_bn1[j] = 0.f; g_bn2[j] = 0.f; }
    for (int j = i; j < BB * HC; j += stride) g_pool[j] = 0.f;
}

// ---------------- graph counts ----------------
__global__ void k_counts(const int* __restrict__ batch) {
    __shared__ int sm[BB];
    int t = threadIdx.x;
    if (t < BB) sm[t] = 0;
    __syncthreads();
    int i = blockIdx.x * blockDim.x + t;
    if (i < NN) atomicAdd(&sm[batch[i]], 1);
    __syncthreads();
    if (t < BB && sm[t]) atomicAdd(&g_counts[t], sm[t]);
}

__global__ void k_graph_meta() {
    if (threadIdx.x == 0 && blockIdx.x == 0) {
        int acc = 0;
        for (int b = 0; b < BB; b++) {
            int c = g_counts[b];
            g_starts[b] = acc;
            acc += c;
            g_gs[b] = (int)ceilf(sqrtf((float)c));
        }
    }
}

// ---------------- CSR build ----------------
__global__ void k_degree(const int* __restrict__ ei) {
    int e = blockIdx.x * blockDim.x + threadIdx.x;
    if (e >= ETOT) return;
    int d = (e < EE) ? ei[EE + e] : (e - EE);
    atomicAdd(&g_deg[d], 1);
}

__global__ void k_scan1() {
    __shared__ int sm[SCAN_B];
    int t = threadIdx.x;
    int i = blockIdx.x * SCAN_B + t;
    int v = (i < NN) ? g_deg[i] : 0;
    sm[t] = v;
    __syncthreads();
    #pragma unroll
    for (int off = 1; off < SCAN_B; off <<= 1) {
        int xv = (t >= off) ? sm[t - off] : 0;
        __syncthreads();
        sm[t] += xv;
        __syncthreads();
    }
    if (i < NN) g_off[i] = sm[t];
    if (t == SCAN_B - 1) g_bsum[blockIdx.x] = sm[t];
}

__global__ void k_scan2() {
    if (threadIdx.x == 0) {
        int run = 0;
        for (int b = 0; b < NBLK; b++) {
            int t = g_bsum[b];
            g_bsum[b] = run;
            run += t;
        }
        g_off[NN] = run;
    }
}

__global__ void k_scan3() {
    int i = blockIdx.x * blockDim.x + threadIdx.x;
    if (i >= NN) return;
    int e = g_off[i] - g_deg[i] + g_bsum[i / SCAN_B];
    g_off[i] = e;
    g_cur[i] = e;
}

__global__ void k_scatter(const int* __restrict__ ei) {
    int e = blockIdx.x * blockDim.x + threadIdx.x;
    if (e >= ETOT) return;
    int s, d;
    if (e < EE) { s = ei[e]; d = ei[EE + e]; }
    else { s = d = e - EE; }
    int p = atomicAdd(&g_cur[d], 1);
    g_csr[p] = s;
}

// ---------------- double-buffered fp16 tensor-core GEMM + fused attn coeffs ------
// C[M,256] = A[M,K] @ B[K,256].  BN=64 == head width -> blockIdx.y == head.
template <int K, bool FUSE_PE, bool A_HALF>
__global__ void k_gemm_tc(const __half* __restrict__ Ah,
                          const float* __restrict__ Bw,
                          __half* __restrict__ C, int M,
                          const float* __restrict__ x, const int* __restrict__ batch,
                          const float* __restrict__ Wpos, const float* __restrict__ bpos,
                          const float* __restrict__ a_src, const float* __restrict__ a_dst) {
    const int BM = 128, BN = 64, BK = 32;
    const int LDAH = 40;             // halves per A row (32 + 8 pad)
    const int LDBH = 72;             // halves per B row (64 + 8 pad)
    const int LDB = BN + 4;          // float epilogue stride
    const int ATILE = BM * LDAH;     // 5120 halves
    const int BTILE = BK * LDBH;     // 2304 halves
    __shared__ __align__(16) char smraw[BM * LDB * 4];   // 34816 B; dbuf uses 29696 B
    float* smf = (float*)smraw;
    __half* base = (__half*)smraw;

    int tid = threadIdx.x;
    int warp = tid >> 5;
    int wm = warp & 3;
    int wn = warp >> 2;
    int row0 = blockIdx.x * BM;
    int col0 = blockIdx.y * BN;

    // per-thread tile coords
    int r = tid >> 1;                // A row 0..127
    int cbase = (tid & 1) * 16;      // A k-offset 0/16
    int kk = tid >> 3;               // B row 0..31
    int cc = (tid & 7) * 8;          // B col 0..56
    int gr = row0 + r;

    wmma::fragment<wmma::accumulator, 16, 16, 16, float> acc[2][2];
    #pragma unroll
    for (int i = 0; i < 2; i++)
        #pragma unroll
        for (int j = 0; j < 2; j++) wmma::fill_fragment(acc[i][j], 0.f);

    float4 ra[4];                    // A prefetch (fp32 path: 16 floats; half path: 2 used)
    float4 rb[2];                    // B prefetch (8 floats)

    const int NIT = (K + BK - 1) / BK;

    // --- tile load into regs (no smem) ---
    auto load_tile = [&](int k0) {
        bool peStage = FUSE_PE && (k0 >= F_IN);
        if (!peStage) {
            if (A_HALF) {
                const float4* src = (const float4*)(Ah + (size_t)gr * K + k0 + cbase);
                if (gr < M) { ra[0] = src[0]; ra[1] = src[1]; }
                else { ra[0] = make_float4(0, 0, 0, 0); ra[1] = ra[0]; }
            } else {
                const float* src = x + (size_t)gr * F_IN + k0 + cbase;   // FUSE_PE fp32 A
                #pragma unroll
                for (int v = 0; v < 4; v++)
                    ra[v] = (gr < M) ? *(const float4*)(src + v * 4)
                                     : make_float4(0, 0, 0, 0);
            }
        }
        #pragma unroll
        for (int v = 0; v < 2; v++) {
            int krow = k0 + kk;
            rb[v] = (krow < K) ? *(const float4*)&Bw[(size_t)krow * HC + col0 + cc + v * 4]
                               : make_float4(0, 0, 0, 0);
        }
    };

    // --- regs -> smem buffer (with conversion / PE generation) ---
    auto store_tile = [&](int k0, int buf) {
        __half* As = base + buf * (ATILE + BTILE);
        __half* Bs = As + ATILE;
        __half* dst = &As[r * LDAH + cbase];
        if (FUSE_PE && k0 >= F_IN) {
            if (cbase == 0) {
                float p0 = 0.f, p1 = 0.f;
                if (gr < M) {
                    int b = batch[gr];
                    int g = g_gs[b];
                    int i = gr - g_starts[b];
                    int rowI = i / g;
                    int colI = i - rowI * g;
                    float denom = (float)(g - 1 > 1 ? g - 1 : 1);
                    p0 = (float)rowI / denom;
                    p1 = (float)colI / denom;
                }
                #pragma unroll
                for (int jj = 0; jj < 16; jj += 2) {
                    float v0 = (gr < M) ? (p0 * Wpos[jj] + p1 * Wpos[POS + jj] + bpos[jj]) : 0.f;
                    float v1 = (gr < M) ? (p0 * Wpos[jj + 1] + p1 * Wpos[POS + jj + 1] + bpos[jj + 1]) : 0.f;
                    *(__half2*)&dst[jj] = __floats2half2_rn(v0, v1);
                }
            } else {
                #pragma unroll
                for (int jj = 0; jj < 16; jj += 8)
                    *(float4*)&dst[jj] = make_float4(0, 0, 0, 0);
            }
        } else if (A_HALF) {
            *(float4*)&dst[0] = ra[0];
            *(float4*)&dst[8] = ra[1];
        } else {
            #pragma unroll
            for (int v = 0; v < 4; v++) {
                *(__half2*)&dst[v * 4]     = __floats2half2_rn(ra[v].x, ra[v].y);
                *(__half2*)&dst[v * 4 + 2] = __floats2half2_rn(ra[v].z, ra[v].w);
            }
        }
        __half* d = &Bs[kk * LDBH + cc];
        *(__half2*)&d[0] = __floats2half2_rn(rb[0].x, rb[0].y);
        *(__half2*)&d[2] = __floats2half2_rn(rb[0].z, rb[0].w);
        *(__half2*)&d[4] = __floats2half2_rn(rb[1].x, rb[1].y);
        *(__half2*)&d[6] = __floats2half2_rn(rb[1].z, rb[1].w);
    };

    // prologue
    load_tile(0);
    store_tile(0, 0);
    __syncthreads();

    for (int it = 0; it < NIT; it++) {
        int cur = it & 1;
        if (it + 1 < NIT) load_tile((it + 1) * BK);

        __half* As = base + cur * (ATILE + BTILE);
        __half* Bs = As + ATILE;
        #pragma unroll
        for (int ks = 0; ks < BK; ks += 16) {
            wmma::fragment<wmma::matrix_a, 16, 16, 16, __half, wmma::row_major> af[2];
            wmma::fragment<wmma::matrix_b, 16, 16, 16, __half, wmma::row_major> bf[2];
            #pragma unroll
            for (int i = 0; i < 2; i++)
                wmma::load_matrix_sync(af[i], &As[(wm * 32 + i * 16) * LDAH + ks], LDAH);
            #pragma unroll
            for (int j = 0; j < 2; j++)
                wmma::load_matrix_sync(bf[j], &Bs[ks * LDBH + wn * 32 + j * 16], LDBH);
            #pragma unroll
            for (int i = 0; i < 2; i++)
                #pragma unroll
                for (int j = 0; j < 2; j++)
                    wmma::mma_sync(acc[i][j], af[i], bf[j], acc[i][j]);
        }

        if (it + 1 < NIT) store_tile((it + 1) * BK, cur ^ 1);
        __syncthreads();
    }

    // ---- epilogue: stage C tile in fp32 smem, fp16 writeout, attn coefficients ----
    #pragma unroll
    for (int i = 0; i < 2; i++)
        #pragma unroll
        for (int j = 0; j < 2; j++)
            wmma::store_matrix_sync(&smf[(wm * 32 + i * 16) * LDB + wn * 32 + j * 16],
                                    acc[i][j], LDB, wmma::mem_row_major);
    __syncthreads();

    for (int e = tid; e < BM * BN / 2; e += 256) {
        int rr = e >> 5;
        int c = (e & 31) * 2;
        int grr = row0 + rr;
        if (grr < M) {
            __half2 hv = __floats2half2_rn(smf[rr * LDB + c], smf[rr * LDB + c + 1]);
            *(__half2*)&C[(size_t)grr * HC + col0 + c] = hv;
        }
    }

    {
        int head = blockIdx.y;
        int halfc = (tid & 1) * 32;
        const float* av = a_src + head * 64;
        const float* dv = a_dst + head * 64;
        float ps = 0.f, pd = 0.f;
        #pragma unroll 8
        for (int k = 0; k < 32; k++) {
            float v = smf[r * LDB + halfc + k];
            ps += v * av[halfc + k];
            pd += v * dv[halfc + k];
        }
        ps += __shfl_xor_sync(0xFFFFFFFFu, ps, 1);
        pd += __shfl_xor_sync(0xFFFFFFFFu, pd, 1);
        if ((tid & 1) == 0 && gr < M) {
            g_as[gr * 4 + head] = ps;
            g_ad[gr * 4 + head] = pd;
        }
    }
}

// ---------------- softmax-aggregate (warp/node, fp16 h, unrolled MLP) + BN stats --
__global__ void k_agg(const __half* __restrict__ h, const float* __restrict__ bias,
                      float* __restrict__ out, float* __restrict__ bnsums) {
    int tid = threadIdx.x;
    int wp = tid >> 5;
    int lane = tid & 31;
    int node = blockIdx.x * 8 + wp;
    __shared__ float wsm[8][32][4];
    __shared__ int   ssm[8][32];
    __shared__ float ssum[HC];
    __shared__ float ssum2[HC];
    ssum[tid] = 0.f;
    ssum2[tid] = 0.f;
    __syncthreads();

    int beg = g_off[node], end = g_off[node + 1];
    float ad0 = g_ad[node * 4 + 0], ad1 = g_ad[node * 4 + 1];
    float ad2 = g_ad[node * 4 + 2], ad3 = g_ad[node * 4 + 3];

    float2 acc0 = {0.f, 0.f}, acc1 = {0.f, 0.f}, acc2 = {0.f, 0.f}, acc3 = {0.f, 0.f};
    float sw0 = 0.f, sw1 = 0.f, sw2 = 0.f, sw3 = 0.f;
    for (int base = beg; base < end; base += 32) {
        int j = base + lane;
        float w0 = 0.f, w1 = 0.f, w2 = 0.f, w3 = 0.f;
        int s = beg < end ? g_csr[(j < end) ? j : beg] : 0;
        if (j < end) {
            const float* as = &g_as[s * 4];
            float v0 = as[0] + ad0; v0 = v0 > 0.f ? v0 : 0.2f * v0; w0 = __expf(v0);
            float v1 = as[1] + ad1; v1 = v1 > 0.f ? v1 : 0.2f * v1; w1 = __expf(v1);
            float v2 = as[2] + ad2; v2 = v2 > 0.f ? v2 : 0.2f * v2; w2 = __expf(v2);
            float v3 = as[3] + ad3; v3 = v3 > 0.f ? v3 : 0.2f * v3; w3 = __expf(v3);
        }
        wsm[wp][lane][0] = w0; wsm[wp][lane][1] = w1;
        wsm[wp][lane][2] = w2; wsm[wp][lane][3] = w3;
        ssm[wp][lane] = s;
        sw0 += w0; sw1 += w1; sw2 += w2; sw3 += w3;
        __syncwarp();
        int cnt = end - base; if (cnt > 32) cnt = 32;
        int cnt4 = (cnt + 3) & ~3;
        for (int t = 0; t < cnt4; t += 4) {
            float2 f[4][4];
            float wv[4][4];
            #pragma unroll
            for (int u = 0; u < 4; u++) {
                int ss = ssm[wp][t + u];
                const __half2* hp = (const __half2*)(h + (size_t)ss * HC) + lane;
                f[u][0] = __half22float2(hp[0]);
                f[u][1] = __half22float2(hp[32]);
                f[u][2] = __half22float2(hp[64]);
                f[u][3] = __half22float2(hp[96]);
                wv[u][0] = wsm[wp][t + u][0];
                wv[u][1] = wsm[wp][t + u][1];
                wv[u][2] = wsm[wp][t + u][2];
                wv[u][3] = wsm[wp][t + u][3];
            }
            #pragma unroll
            for (int u = 0; u < 4; u++) {
                acc0.x += wv[u][0] * f[u][0].x; acc0.y += wv[u][0] * f[u][0].y;
                acc1.x += wv[u][1] * f[u][1].x; acc1.y += wv[u][1] * f[u][1].y;
                acc2.x += wv[u][2] * f[u][2].x; acc2.y += wv[u][2] * f[u][2].y;
                acc3.x += wv[u][3] * f[u][3].x; acc3.y += wv[u][3] * f[u][3].y;
            }
        }
        __syncwarp();
    }
    #pragma unroll
    for (int off = 16; off; off >>= 1) {
        sw0 += __shfl_xor_sync(0xFFFFFFFFu, sw0, off);
        sw1 += __shfl_xor_sync(0xFFFFFFFFu, sw1, off);
        sw2 += __shfl_xor_sync(0xFFFFFFFFu, sw2, off);
        sw3 += __shfl_xor_sync(0xFFFFFFFFu, sw3, off);
    }
    float i0 = 1.f / sw0, i1 = 1.f / sw1, i2 = 1.f / sw2, i3 = 1.f / sw3;
    int c0 = 2 * lane;
    float2 r0, r1, r2, r3;
    r0.x = acc0.x * i0 + bias[c0];        r0.y = acc0.y * i0 + bias[c0 + 1];
    r1.x = acc1.x * i1 + bias[c0 + 64];   r1.y = acc1.y * i1 + bias[c0 + 65];
    r2.x = acc2.x * i2 + bias[c0 + 128];  r2.y = acc2.y * i2 + bias[c0 + 129];
    r3.x = acc3.x * i3 + bias[c0 + 192];  r3.y = acc3.y * i3 + bias[c0 + 193];
    float* op = &out[(size_t)node * HC];
    *(float2*)&op[c0]       = r0;
    *(float2*)&op[c0 + 64]  = r1;
    *(float2*)&op[c0 + 128] = r2;
    *(float2*)&op[c0 + 192] = r3;
    atomicAdd(&ssum[c0], r0.x);        atomicAdd(&ssum[c0 + 1], r0.y);
    atomicAdd(&ssum[c0 + 64], r1.x);   atomicAdd(&ssum[c0 + 65], r1.y);
    atomicAdd(&ssum[c0 + 128], r2.x);  atomicAdd(&ssum[c0 + 129], r2.y);
    atomicAdd(&ssum[c0 + 192], r3.x);  atomicAdd(&ssum[c0 + 193], r3.y);
    atomicAdd(&ssum2[c0], r0.x * r0.x);        atomicAdd(&ssum2[c0 + 1], r0.y * r0.y);
    atomicAdd(&ssum2[c0 + 64], r1.x * r1.x);   atomicAdd(&ssum2[c0 + 65], r1.y * r1.y);
    atomicAdd(&ssum2[c0 + 128], r2.x * r2.x);  atomicAdd(&ssum2[c0 + 129], r2.y * r2.y);
    atomicAdd(&ssum2[c0 + 192], r3.x * r3.x);  atomicAdd(&ssum2[c0 + 193], r3.y * r3.y);
    __syncthreads();
    atomicAdd(&bnsums[tid], ssum[tid]);
    atomicAdd(&bnsums[HC + tid], ssum2[tid]);
}

// ---------------- batch norm finalize ----------------
__global__ void k_bn_fin(const float* __restrict__ sums, const float* __restrict__ gamma,
                         const float* __restrict__ beta, float* __restrict__ prm) {
    int ch = threadIdx.x;
    float mean = sums[ch] / (float)NN;
    float var = sums[HC + ch] / (float)NN - mean * mean;
    float inv = rsqrtf(var + 1e-5f);
    float sc = gamma[ch] * inv;
    prm[ch] = sc;
    prm[HC + ch] = beta[ch] - mean * sc;
}

// BN+ELU: fp32 in -> fp16 out (feeds GEMM2 A only)
__global__ void k_bn_elu(const float* __restrict__ x, const float* __restrict__ prm,
                         __half* __restrict__ xo) {
    long i4 = (long)blockIdx.x * blockDim.x + threadIdx.x;
    if (i4 >= (long)NN * HC / 4) return;
    int ch = (int)(i4 & (HC / 4 - 1)) * 4;
    float4 v = *(const float4*)&x[i4 * 4];
    float4 s = *(const float4*)&prm[ch];
    float4 o = *(const float4*)&prm[HC + ch];
    v.x = v.x * s.x + o.x; v.x = v.x > 0.f ? v.x : (__expf(v.x) - 1.f);
    v.y = v.y * s.y + o.y; v.y = v.y > 0.f ? v.y : (__expf(v.y) - 1.f);
    v.z = v.z * s.z + o.z; v.z = v.z > 0.f ? v.z : (__expf(v.z) - 1.f);
    v.w = v.w * s.w + o.w; v.w = v.w > 0.f ? v.w : (__expf(v.w) - 1.f);
    __half2 h0 = __floats2half2_rn(v.x, v.y);
    __half2 h1 = __floats2half2_rn(v.z, v.w);
    *(__half2*)&xo[i4 * 4]     = h0;
    *(__half2*)&xo[i4 * 4 + 2] = h1;
}

// layer 2: BN+ELU fused directly into pooling (no activation writeback)
__global__ void k_bn_elu_pool(const float* __restrict__ x, const float* __restrict__ prm,
                              const int* __restrict__ batch) {
    int ch = threadIdx.x;
    int r0 = blockIdx.x * 128;
    int rend = r0 + 128; if (rend > NN) rend = NN;
    float sc = prm[ch], of = prm[HC + ch];
    float acc = 0.f;
    int gcur = batch[r0];
    for (int r = r0; r < rend; r++) {
        int g = batch[r];
        if (g != gcur) {
            atomicAdd(&g_pool[gcur * HC + ch], acc);
            acc = 0.f;
            gcur = g;
        }
        float v = x[(size_t)r * HC + ch] * sc + of;
        acc += (v > 0.f ? v : (__expf(v) - 1.f));
    }
    atomicAdd(&g_pool[gcur * HC + ch], acc);
}

__global__ void k_fc(const float* __restrict__ Wfc, const float* __restrict__ bfc,
                     float* __restrict__ out) {
    int g = blockIdx.x, o = threadIdx.x;
    __shared__ float ps[HC];
    float invc = 1.f / (float)g_counts[g];
    for (int c = o; c < HC; c += OUT_DIM) ps[c] = g_pool[g * HC + c] * invc;
    __syncthreads();
    float acc = bfc[o];
    #pragma unroll 8
    for (int c = 0; c < HC; c++) acc += ps[c] * Wfc[c * OUT_DIM + o];
    out[g * OUT_DIM + o] = acc;
}

// ---------------- launch ----------------
extern "C" void kernel_launch(void* const* d_in, const int* in_sizes, int n_in,
                              void* d_out, int out_size) {
    const float* x       = (const float*)d_in[0];
    const int*   ei      = (const int*)d_in[1];
    const int*   batch   = (const int*)d_in[2];
    const float* W_pos   = (const float*)d_in[3];
    const float* b_pos   = (const float*)d_in[4];
    const float* W1      = (const float*)d_in[5];
    const float* a_src1  = (const float*)d_in[6];
    const float* a_dst1  = (const float*)d_in[7];
    const float* b1      = (const float*)d_in[8];
    const float* gamma1  = (const float*)d_in[9];
    const float* beta1   = (const float*)d_in[10];
    const float* W2      = (const float*)d_in[11];
    const float* a_src2  = (const float*)d_in[12];
    const float* a_dst2  = (const float*)d_in[13];
    const float* b2      = (const float*)d_in[14];
    const float* gamma2  = (const float*)d_in[15];
    const float* beta2   = (const float*)d_in[16];
    const float* W_fc    = (const float*)d_in[17];
    const float* b_fc    = (const float*)d_in[18];
    float* out = (float*)d_out;

    __half *hH, *xH;
    float *hF, *bn1, *bn2, *prm1, *prm2;
    cudaGetSymbolAddress((void**)&hH, g_hH);
    cudaGetSymbolAddress((void**)&xH, g_xH);
    cudaGetSymbolAddress((void**)&hF, g_hF);
    cudaGetSymbolAddress((void**)&bn1, g_bn1);
    cudaGetSymbolAddress((void**)&bn2, g_bn2);
    cudaGetSymbolAddress((void**)&prm1, g_prm1);
    cudaGetSymbolAddress((void**)&prm2, g_prm2);

    // ---- common zero pass ----
    k_zero<<<256, 256>>>();

    // ---- fork: CSR build on side stream, concurrent with meta + GEMM1 ----
    cudaEventRecord(g_evFork, 0);
    cudaStreamWaitEvent(g_s2, g_evFork, 0);

    k_degree<<<(ETOT + 255) / 256, 256, 0, g_s2>>>(ei);
    k_scan1<<<NBLK, SCAN_B, 0, g_s2>>>();
    k_scan2<<<1, 32, 0, g_s2>>>();
    k_scan3<<<(NN + 255) / 256, 256, 0, g_s2>>>();
    k_scatter<<<(ETOT + 255) / 256, 256, 0, g_s2>>>(ei);

    // main stream: graph meta + layer-1 GEMM (PE + attn fused)
    k_counts<<<(NN + 255) / 256, 256>>>(batch);
    k_graph_meta<<<1, 32>>>();

    dim3 gg((NN + 127) / 128, HC / 64);
    k_gemm_tc<ENH, true, false><<<gg, 256>>>(nullptr, W1, hH, NN,
                                             x, batch, W_pos, b_pos, a_src1, a_dst1);

    // ---- join: agg needs the CSR ----
    cudaEventRecord(g_evJoin, g_s2);
    cudaStreamWaitEvent(0, g_evJoin, 0);

    k_agg<<<NN / 8, 256>>>(hH, b1, hF, bn1);
    k_bn_fin<<<1, 256>>>(bn1, gamma1, beta1, prm1);
    k_bn_elu<<<(int)(((long)NN * HC / 4 + 255) / 256), 256>>>(hF, prm1, xH);

    // layer 2 (fp16 A operand)
    k_gemm_tc<HC, false, true><<<gg, 256>>>(xH, W2, hH, NN,
                                            nullptr, nullptr, nullptr, nullptr, a_src2, a_dst2);
    k_agg<<<NN / 8, 256>>>(hH, b2, hF, bn2);
    k_bn_fin<<<1, 256>>>(bn2, gamma2, beta2, prm2);

    // fused BN+ELU+pool
    k_bn_elu_pool<<<(NN + 127) / 128, 256>>>(hF, prm2, batch);
    k_fc<<<BB, OUT_DIM>>>(W_fc, b_fc, out);
}